// round 2
// baseline (speedup 1.0000x reference)
#include <cuda_runtime.h>

#define B_  256
#define C_  384
#define N_  256
#define NH  12
#define HD  32
#define H3  1152

__device__ __constant__ float kSCALE = 0.17677669529663687f; // 32^-0.5

// Scratch (module-load allocated; no runtime allocation)
__device__ float g_Q[B_ * NH * N_ * HD];   // (b,h,n,d)
__device__ float g_K[B_ * NH * N_ * HD];
__device__ float g_V[B_ * NH * N_ * HD];
__device__ float g_AO[B_ * N_ * C_];       // (b,n,c) attention output

// ---------------------------------------------------------------------------
// QKV GEMM:  qkv[b,n,o] = sum_c x[b,c,n] * w[o,c] + bias[o]
// scatter into g_Q/g_K/g_V as (b,h,n,d)
// Tile: 64(m=n) x 64(o), K-step 16, 256 threads, 4x4 micro-tile
// ---------------------------------------------------------------------------
__global__ __launch_bounds__(256) void qkv_kernel(const float* __restrict__ x,
                                                  const float* __restrict__ w,
                                                  const float* __restrict__ bias)
{
    __shared__ float As[16][64];   // As[k][m]
    __shared__ float Bs[16][68];   // Bs[k][o] padded

    const int b  = blockIdx.z;
    const int m0 = blockIdx.y * 64;
    const int o0 = blockIdx.x * 64;
    const int tid = threadIdx.x;
    const int tx = tid & 15;       // o micro
    const int ty = tid >> 4;       // m micro

    const float* xb = x + (size_t)b * C_ * N_;

    const int am = tid & 63, ak = tid >> 6;   // A loader: m fastest (coalesced over n)
    const int bk = tid & 15, bo = tid >> 4;   // B loader: k fastest (coalesced over c)

    float acc[4][4] = {};

    for (int k0 = 0; k0 < C_; k0 += 16) {
#pragma unroll
        for (int p = 0; p < 4; p++)
            As[ak + 4 * p][am] = xb[(k0 + ak + 4 * p) * N_ + m0 + am];
#pragma unroll
        for (int p = 0; p < 4; p++)
            Bs[bk][bo + 16 * p] = w[(o0 + bo + 16 * p) * C_ + k0 + bk];
        __syncthreads();

#pragma unroll
        for (int k = 0; k < 16; k++) {
            float4 af = *(const float4*)&As[k][ty * 4];
            float4 bf = *(const float4*)&Bs[k][tx * 4];
            float ar[4] = {af.x, af.y, af.z, af.w};
            float br[4] = {bf.x, bf.y, bf.z, bf.w};
#pragma unroll
            for (int i = 0; i < 4; i++)
#pragma unroll
                for (int j = 0; j < 4; j++)
                    acc[i][j] += ar[i] * br[j];
        }
        __syncthreads();
    }

    // Epilogue: bias + scatter. 4 consecutive o stay inside one head (4 | tx*4).
    const int oBase = o0 + tx * 4;
    const int s   = oBase / C_;
    const int rem = oBase - s * C_;
    const int h   = rem >> 5;
    const int d   = rem & 31;
    float* base = (s == 0 ? g_Q : (s == 1 ? g_K : g_V));
    float* dst  = base + ((size_t)(b * NH + h)) * (N_ * HD);

    const float b0 = bias[oBase + 0], b1 = bias[oBase + 1];
    const float b2 = bias[oBase + 2], b3 = bias[oBase + 3];

#pragma unroll
    for (int i = 0; i < 4; i++) {
        const int m = m0 + ty * 4 + i;
        float4 v;
        v.x = acc[i][0] + b0;
        v.y = acc[i][1] + b1;
        v.z = acc[i][2] + b2;
        v.w = acc[i][3] + b3;
        *(float4*)&dst[m * HD + d] = v;
    }
}

// ---------------------------------------------------------------------------
// Attention: one CTA per (b,h). K,V staged in smem (64 KB dynamic).
// One thread per query row; two-pass online softmax with clip.
// ---------------------------------------------------------------------------
__global__ __launch_bounds__(256) void attn_kernel()
{
    extern __shared__ float sm[];
    float* Ks = sm;            // 256*32
    float* Vs = sm + 8192;     // 256*32

    const int bh  = blockIdx.x;
    const int tid = threadIdx.x;

    const float* Qg = g_Q + (size_t)bh * (N_ * HD);
    const float* Kg = g_K + (size_t)bh * (N_ * HD);
    const float* Vg = g_V + (size_t)bh * (N_ * HD);

    // cooperative coalesced copy of K and V
    for (int i = tid; i < (N_ * HD) / 4; i += 256) {
        ((float4*)Ks)[i] = ((const float4*)Kg)[i];
        ((float4*)Vs)[i] = ((const float4*)Vg)[i];
    }
    __syncthreads();

    // normalize K row `tid`
    {
        float* kr = Ks + tid * HD;
        float ss = 0.f;
#pragma unroll
        for (int j = 0; j < HD; j++) ss += kr[j] * kr[j];
        const float inv = 1.f / fmaxf(sqrtf(ss), 1e-12f);
#pragma unroll
        for (int j = 0; j < HD; j++) kr[j] *= inv;
    }

    // own q row: load, normalize, fold in SCALE
    float4 q[8];
    {
        const float4* qg = (const float4*)(Qg + tid * HD);
        float ss = 0.f;
#pragma unroll
        for (int j = 0; j < 8; j++) {
            q[j] = qg[j];
            ss += q[j].x * q[j].x + q[j].y * q[j].y + q[j].z * q[j].z + q[j].w * q[j].w;
        }
        const float inv = kSCALE / fmaxf(sqrtf(ss), 1e-12f);
#pragma unroll
        for (int j = 0; j < 8; j++) {
            q[j].x *= inv; q[j].y *= inv; q[j].z *= inv; q[j].w *= inv;
        }
    }
    __syncthreads();

    // pass 1: online max + sum of exp
    float maxv = -1e30f, sumv = 0.f;
    for (int m = 0; m < N_; m++) {
        const float4* kp = (const float4*)(Ks + m * HD);
        float s = 0.f;
#pragma unroll
        for (int j = 0; j < 8; j++) {
            float4 k4 = kp[j];
            s += q[j].x * k4.x + q[j].y * k4.y + q[j].z * k4.z + q[j].w * k4.w;
        }
        const float nm = fmaxf(maxv, s);
        sumv = sumv * __expf(maxv - nm) + __expf(s - nm);
        maxv = nm;
    }
    const float invs = 1.f / sumv;

    // pass 2: recompute scores, clip softmax, accumulate P*V
    float4 acc[8];
#pragma unroll
    for (int j = 0; j < 8; j++) acc[j] = make_float4(0.f, 0.f, 0.f, 0.f);

    for (int m = 0; m < N_; m++) {
        const float4* kp = (const float4*)(Ks + m * HD);
        float s = 0.f;
#pragma unroll
        for (int j = 0; j < 8; j++) {
            float4 k4 = kp[j];
            s += q[j].x * k4.x + q[j].y * k4.y + q[j].z * k4.z + q[j].w * k4.w;
        }
        float p = __expf(s - maxv) * invs;
        p = fminf(fmaxf(p, 1e-6f), 1.f);
        const float4* vp = (const float4*)(Vs + m * HD);
#pragma unroll
        for (int j = 0; j < 8; j++) {
            float4 v4 = vp[j];
            acc[j].x += p * v4.x;
            acc[j].y += p * v4.y;
            acc[j].z += p * v4.z;
            acc[j].w += p * v4.w;
        }
    }

    const int b = bh / NH, h = bh - (bh / NH) * NH;
    float4* dst = (float4*)(g_AO + (size_t)b * (N_ * C_) + tid * C_ + h * HD);
#pragma unroll
    for (int j = 0; j < 8; j++) dst[j] = acc[j];
}

// ---------------------------------------------------------------------------
// Proj GEMM: out[b,o,n] = sum_c AO[b,n,c] * w[o,c] + bias[o]
// ---------------------------------------------------------------------------
__global__ __launch_bounds__(256) void proj_kernel(const float* __restrict__ w,
                                                   const float* __restrict__ bias,
                                                   float* __restrict__ out)
{
    __shared__ float As[16][68];   // As[k][m] padded (k-fastest loads)
    __shared__ float Bs[16][68];   // Bs[k][o] padded

    const int b  = blockIdx.z;
    const int m0 = blockIdx.y * 64;
    const int o0 = blockIdx.x * 64;
    const int tid = threadIdx.x;
    const int tx = tid & 15;
    const int ty = tid >> 4;

    const float* A = g_AO + (size_t)b * (N_ * C_);

    const int lk = tid & 15, lr = tid >> 4;   // k fastest (coalesced over c)

    float acc[4][4] = {};

    for (int k0 = 0; k0 < C_; k0 += 16) {
#pragma unroll
        for (int p = 0; p < 4; p++)
            As[lk][lr + 16 * p] = A[(m0 + lr + 16 * p) * C_ + k0 + lk];
#pragma unroll
        for (int p = 0; p < 4; p++)
            Bs[lk][lr + 16 * p] = w[(o0 + lr + 16 * p) * C_ + k0 + lk];
        __syncthreads();

#pragma unroll
        for (int k = 0; k < 16; k++) {
            float4 af = *(const float4*)&As[k][ty * 4];
            float4 bf = *(const float4*)&Bs[k][tx * 4];
            float ar[4] = {af.x, af.y, af.z, af.w};
            float br[4] = {bf.x, bf.y, bf.z, bf.w};
#pragma unroll
            for (int i = 0; i < 4; i++)
#pragma unroll
                for (int j = 0; j < 4; j++)
                    acc[i][j] += ar[i] * br[j];
        }
        __syncthreads();
    }

    // Epilogue: out layout (b, o, n) — store float4 along n (m contiguous).
    float* ob = out + (size_t)b * C_ * N_;
#pragma unroll
    for (int j = 0; j < 4; j++) {
        const int o = o0 + tx * 4 + j;
        const float bo = bias[o];
        float4 v;
        v.x = acc[0][j] + bo;
        v.y = acc[1][j] + bo;
        v.z = acc[2][j] + bo;
        v.w = acc[3][j] + bo;
        *(float4*)&ob[o * N_ + m0 + ty * 4] = v;
    }
}

// ---------------------------------------------------------------------------
extern "C" void kernel_launch(void* const* d_in, const int* in_sizes, int n_in,
                              void* d_out, int out_size)
{
    const float* x      = (const float*)d_in[0];
    const float* qkv_w  = (const float*)d_in[1];
    const float* qkv_b  = (const float*)d_in[2];
    const float* proj_w = (const float*)d_in[3];
    const float* proj_b = (const float*)d_in[4];
    float* out = (float*)d_out;

    cudaFuncSetAttribute(attn_kernel, cudaFuncAttributeMaxDynamicSharedMemorySize, 65536);

    qkv_kernel<<<dim3(H3 / 64, N_ / 64, B_), 256>>>(x, qkv_w, qkv_b);
    attn_kernel<<<B_ * NH, 256, 65536>>>();
    proj_kernel<<<dim3(C_ / 64, N_ / 64, B_), 256>>>(proj_w, proj_b, out);
}

// round 5
// speedup vs baseline: 2.5374x; 2.5374x over previous
#include <cuda_runtime.h>
#include <cuda_bf16.h>
#include <cstdint>

#define B_  256
#define C_  384
#define N_  256
#define NH  12
#define HD  32
#define H3  1152

__device__ __constant__ float kSCALE = 0.17677669529663687f; // 32^-0.5

// ---------------- scratch (module-load allocated) ----------------
__device__ float g_Q[B_ * NH * N_ * HD];   // (b,h,n,d) fp32
__device__ float g_K[B_ * NH * N_ * HD];
__device__ float g_V[B_ * NH * N_ * HD];
__device__ __nv_bfloat16 g_Xhi[B_ * N_ * C_];   // (b,n,c)
__device__ __nv_bfloat16 g_Xlo[B_ * N_ * C_];
__device__ __nv_bfloat16 g_AOhi[B_ * N_ * C_];  // attention out (b,n,c)
__device__ __nv_bfloat16 g_AOlo[B_ * N_ * C_];
__device__ __nv_bfloat16 g_Wqhi[H3 * C_];
__device__ __nv_bfloat16 g_Wqlo[H3 * C_];
__device__ __nv_bfloat16 g_Wphi[C_ * C_];
__device__ __nv_bfloat16 g_Wplo[C_ * C_];

// ---------------- baseline-PTX helpers (no sm_103a-only features) ----------
__device__ __forceinline__ uint32_t smem_u32(const void* p) {
    uint32_t a;
    asm("{ .reg .u64 t; cvta.to.shared.u64 t, %1; cvt.u32.u64 %0, t; }" : "=r"(a) : "l"(p));
    return a;
}
__device__ __forceinline__ void cp16(uint32_t dst, const void* src) {
    asm volatile("cp.async.cg.shared.global [%0], [%1], 16;" :: "r"(dst), "l"(src));
}
__device__ __forceinline__ void cp_commit() {
    asm volatile("cp.async.commit_group;" ::: "memory");
}
template <int N>
__device__ __forceinline__ void cp_wait() {
    asm volatile("cp.async.wait_group %0;" :: "n"(N) : "memory");
}
__device__ __forceinline__ void ldm_x4(uint32_t* r, uint32_t addr) {
    asm volatile("ldmatrix.sync.aligned.m8n8.x4.shared.b16 {%0,%1,%2,%3}, [%4];"
                 : "=r"(r[0]), "=r"(r[1]), "=r"(r[2]), "=r"(r[3]) : "r"(addr));
}
__device__ __forceinline__ void mma16816(float* d, const uint32_t* a, uint32_t b0, uint32_t b1) {
    asm volatile("mma.sync.aligned.m16n8k16.row.col.f32.bf16.bf16.f32 "
                 "{%0,%1,%2,%3}, {%4,%5,%6,%7}, {%8,%9}, {%0,%1,%2,%3};"
                 : "+f"(d[0]), "+f"(d[1]), "+f"(d[2]), "+f"(d[3])
                 : "r"(a[0]), "r"(a[1]), "r"(a[2]), "r"(a[3]), "r"(b0), "r"(b1));
}

// Swizzled tile layout: 128 rows x 32 bf16 (64B/row), packed as row-pairs of
// 128B with 8 swizzled 16B chunks -> conflict-free ldmatrix.
__device__ __forceinline__ uint32_t tile_off(int row, int c) {
    return ((row >> 1) << 7) + ((((((row & 1) << 2) | c)) ^ ((row >> 1) & 7)) << 4);
}

#define OFF_AH 0
#define OFF_AL 8192
#define OFF_BH 16384
#define OFF_BL 24576
#define STAGE  32768
#define SM_TOTAL (2 * STAGE)

// ---------------------------------------------------------------------------
// convert_w: fp32 weights -> bf16 hi/lo
// ---------------------------------------------------------------------------
__global__ __launch_bounds__(256) void convert_w(const float* __restrict__ qw,
                                                 const float* __restrict__ pw)
{
    const int i = blockIdx.x * 256 + threadIdx.x;
    if (i < H3 * C_) {
        float v = qw[i];
        __nv_bfloat16 hi = __float2bfloat16_rn(v);
        g_Wqhi[i] = hi;
        g_Wqlo[i] = __float2bfloat16_rn(v - __bfloat162float(hi));
    }
    const int j = i - H3 * C_;
    if (j >= 0 && j < C_ * C_) {
        float v = pw[j];
        __nv_bfloat16 hi = __float2bfloat16_rn(v);
        g_Wphi[j] = hi;
        g_Wplo[j] = __float2bfloat16_rn(v - __bfloat162float(hi));
    }
}

// ---------------------------------------------------------------------------
// convert_x: x (b,c,n) fp32 -> (b,n,c) bf16 hi/lo via smem transpose
// ---------------------------------------------------------------------------
__global__ __launch_bounds__(256) void convert_x(const float* __restrict__ x)
{
    __shared__ float tile[32][33];
    const int b = blockIdx.z, c0 = blockIdx.x * 32, n0 = blockIdx.y * 32;
    const int tx = threadIdx.x & 31, ty = threadIdx.x >> 5;
    const float* xb = x + (size_t)b * C_ * N_;
#pragma unroll
    for (int r = 0; r < 4; r++) {
        int c = ty + r * 8;
        tile[c][tx] = xb[(size_t)(c0 + c) * N_ + n0 + tx];
    }
    __syncthreads();
#pragma unroll
    for (int r = 0; r < 4; r++) {
        int n = ty + r * 8;
        float v = tile[tx][n];
        __nv_bfloat16 hi = __float2bfloat16_rn(v);
        size_t o = (size_t)b * N_ * C_ + (size_t)(n0 + n) * C_ + c0 + tx;
        g_Xhi[o] = hi;
        g_Xlo[o] = __float2bfloat16_rn(v - __bfloat162float(hi));
    }
}

// ---------------------------------------------------------------------------
// HMMA split-bf16 GEMM:  D[m,o] = sum_c A[m,c]*B[o,c]  (both K-major)
// CTA tile 128x128, K chunk 32, 8 warps of 32m x 64n, cp.async double buffer.
// MODE 0: A=g_X, B=g_Wq -> +bias, scatter g_Q/K/V (b,h,n,d)
// MODE 1: A=g_AO, B=g_Wp -> +bias, store out (b,o,n)
// ---------------------------------------------------------------------------
__device__ __forceinline__ void load_chunk(uint32_t sbase,
                                           const char* pAh, const char* pAl,
                                           const char* pBh, const char* pBl,
                                           int kB, int tid)
{
#pragma unroll
    for (int t = 0; t < 2; t++) {
        const int i = t * 256 + tid;
        const int row = i >> 2, c = i & 3;
        const uint32_t off = tile_off(row, c);
        const size_t g = (size_t)row * (C_ * 2) + kB + c * 16;
        cp16(sbase + OFF_AH + off, pAh + g);
        cp16(sbase + OFF_AL + off, pAl + g);
        cp16(sbase + OFF_BH + off, pBh + g);
        cp16(sbase + OFF_BL + off, pBl + g);
    }
    cp_commit();
}

__device__ __forceinline__ void compute_chunk(uint32_t sbase, int wm, int wn, int lane,
                                              float acc[2][8][4])
{
    const int ldrow = lane & 15;
    const int ldc   = lane >> 4;
#pragma unroll
    for (int kk = 0; kk < 2; kk++) {
        uint32_t ah[2][4], al[2][4], bh[4][4], bl[4][4];
        const int c = kk * 2 + ldc;
#pragma unroll
        for (int mi = 0; mi < 2; mi++) {
            const int row = wm * 32 + mi * 16 + ldrow;
            const uint32_t off = tile_off(row, c);
            ldm_x4(ah[mi], sbase + OFF_AH + off);
            ldm_x4(al[mi], sbase + OFF_AL + off);
        }
#pragma unroll
        for (int nj4 = 0; nj4 < 4; nj4++) {
            const int row = wn * 64 + nj4 * 16 + ldrow;
            const uint32_t off = tile_off(row, c);
            ldm_x4(bh[nj4], sbase + OFF_BH + off);
            ldm_x4(bl[nj4], sbase + OFF_BL + off);
        }
#pragma unroll
        for (int mi = 0; mi < 2; mi++)
#pragma unroll
            for (int nj = 0; nj < 8; nj++) {
                const int g = nj >> 1, p = nj & 1;
                mma16816(acc[mi][nj], ah[mi], bh[g][p], bh[g][p + 2]);
                mma16816(acc[mi][nj], ah[mi], bl[g][p], bl[g][p + 2]);
                mma16816(acc[mi][nj], al[mi], bh[g][p], bh[g][p + 2]);
            }
    }
}

template <int MODE>
__global__ __launch_bounds__(256) void gemm_kernel(const float* __restrict__ bias,
                                                   float* __restrict__ out)
{
    extern __shared__ char sm[];
    const uint32_t sb = smem_u32(sm);
    const int tid = threadIdx.x, lane = tid & 31, wid = tid >> 5;
    const int wm = wid >> 1, wn = wid & 1;
    const int b = blockIdx.z, m0 = blockIdx.y * 128, o0 = blockIdx.x * 128;

    const __nv_bfloat16* Ahi = (MODE == 0) ? g_Xhi : g_AOhi;
    const __nv_bfloat16* Alo = (MODE == 0) ? g_Xlo : g_AOlo;
    const __nv_bfloat16* Bhi = (MODE == 0) ? g_Wqhi : g_Wphi;
    const __nv_bfloat16* Blo = (MODE == 0) ? g_Wqlo : g_Wplo;

    const char* pAh = (const char*)(Ahi + ((size_t)b * N_ + m0) * C_);
    const char* pAl = (const char*)(Alo + ((size_t)b * N_ + m0) * C_);
    const char* pBh = (const char*)(Bhi + (size_t)o0 * C_);
    const char* pBl = (const char*)(Blo + (size_t)o0 * C_);

    float acc[2][8][4] = {};

    load_chunk(sb, pAh, pAl, pBh, pBl, 0, tid);

#pragma unroll 1
    for (int ck = 0; ck < 12; ck++) {
        if (ck < 11) {
            load_chunk(sb + ((ck + 1) & 1) * STAGE, pAh, pAl, pBh, pBl, (ck + 1) * 64, tid);
            cp_wait<1>();
        } else {
            cp_wait<0>();
        }
        __syncthreads();
        compute_chunk(sb + (ck & 1) * STAGE, wm, wn, lane, acc);
        __syncthreads();
    }

    if (MODE == 0) {
#pragma unroll
        for (int mi = 0; mi < 2; mi++) {
            const int m = m0 + wm * 32 + mi * 16 + (lane >> 2);
#pragma unroll
            for (int nj = 0; nj < 8; nj++) {
                const int o = o0 + wn * 64 + nj * 8 + (lane & 3) * 2;
                const int s = o / C_;
                const int rem = o - s * C_;
                const int h = rem >> 5, d = rem & 31;
                float* base = (s == 0) ? g_Q : (s == 1) ? g_K : g_V;
                const float b0 = bias[o], b1 = bias[o + 1];
                float* p0 = base + ((size_t)(b * NH + h) * N_ + m) * HD + d;
                *(float2*)p0 = make_float2(acc[mi][nj][0] + b0, acc[mi][nj][1] + b1);
                *(float2*)(p0 + 8 * HD) = make_float2(acc[mi][nj][2] + b0, acc[mi][nj][3] + b1);
            }
        }
    } else {
        float* ob = out + (size_t)b * C_ * N_;
#pragma unroll
        for (int mi = 0; mi < 2; mi++) {
            const int m = m0 + wm * 32 + mi * 16 + (lane >> 2);
#pragma unroll
            for (int nj = 0; nj < 8; nj++) {
                const int o = o0 + wn * 64 + nj * 8 + (lane & 3) * 2;
                const float b0 = bias[o], b1 = bias[o + 1];
                ob[(size_t)o * N_ + m]           = acc[mi][nj][0] + b0;
                ob[(size_t)(o + 1) * N_ + m]     = acc[mi][nj][1] + b1;
                ob[(size_t)o * N_ + m + 8]       = acc[mi][nj][2] + b0;
                ob[(size_t)(o + 1) * N_ + m + 8] = acc[mi][nj][3] + b1;
            }
        }
    }
}

// ---------------------------------------------------------------------------
// Attention: one CTA per (b,h). K,V staged in smem. One thread per query row.
// Two-pass online softmax with clip. Writes bf16 hi/lo (b,n,c) for proj GEMM.
// ---------------------------------------------------------------------------
__global__ __launch_bounds__(256) void attn_kernel()
{
    extern __shared__ float smf[];
    float* Ks = smf;            // 256*32
    float* Vs = smf + 8192;     // 256*32

    const int bh = blockIdx.x;
    const int tid = threadIdx.x;

    const float* Qg = g_Q + (size_t)bh * (N_ * HD);
    const float* Kg = g_K + (size_t)bh * (N_ * HD);
    const float* Vg = g_V + (size_t)bh * (N_ * HD);

    for (int i = tid; i < (N_ * HD) / 4; i += 256) {
        ((float4*)Ks)[i] = ((const float4*)Kg)[i];
        ((float4*)Vs)[i] = ((const float4*)Vg)[i];
    }
    __syncthreads();

    {   // normalize K row `tid`
        float* kr = Ks + tid * HD;
        float ss = 0.f;
#pragma unroll
        for (int j = 0; j < HD; j++) ss += kr[j] * kr[j];
        const float inv = 1.f / fmaxf(sqrtf(ss), 1e-12f);
#pragma unroll
        for (int j = 0; j < HD; j++) kr[j] *= inv;
    }

    float4 q[8];
    {
        const float4* qg = (const float4*)(Qg + tid * HD);
        float ss = 0.f;
#pragma unroll
        for (int j = 0; j < 8; j++) {
            q[j] = qg[j];
            ss += q[j].x * q[j].x + q[j].y * q[j].y + q[j].z * q[j].z + q[j].w * q[j].w;
        }
        const float inv = kSCALE / fmaxf(sqrtf(ss), 1e-12f);
#pragma unroll
        for (int j = 0; j < 8; j++) {
            q[j].x *= inv; q[j].y *= inv; q[j].z *= inv; q[j].w *= inv;
        }
    }
    __syncthreads();

    float maxv = -1e30f, sumv = 0.f;
    for (int m = 0; m < N_; m++) {
        const float4* kp = (const float4*)(Ks + m * HD);
        float s = 0.f;
#pragma unroll
        for (int j = 0; j < 8; j++) {
            float4 k4 = kp[j];
            s += q[j].x * k4.x + q[j].y * k4.y + q[j].z * k4.z + q[j].w * k4.w;
        }
        const float nm = fmaxf(maxv, s);
        sumv = sumv * __expf(maxv - nm) + __expf(s - nm);
        maxv = nm;
    }
    const float invs = 1.f / sumv;

    float4 acc[8];
#pragma unroll
    for (int j = 0; j < 8; j++) acc[j] = make_float4(0.f, 0.f, 0.f, 0.f);

    for (int m = 0; m < N_; m++) {
        const float4* kp = (const float4*)(Ks + m * HD);
        float s = 0.f;
#pragma unroll
        for (int j = 0; j < 8; j++) {
            float4 k4 = kp[j];
            s += q[j].x * k4.x + q[j].y * k4.y + q[j].z * k4.z + q[j].w * k4.w;
        }
        float p = __expf(s - maxv) * invs;
        p = fminf(fmaxf(p, 1e-6f), 1.f);
        const float4* vp = (const float4*)(Vs + m * HD);
#pragma unroll
        for (int j = 0; j < 8; j++) {
            float4 v4 = vp[j];
            acc[j].x += p * v4.x;
            acc[j].y += p * v4.y;
            acc[j].z += p * v4.z;
            acc[j].w += p * v4.w;
        }
    }

    const int b = bh / NH, h = bh - (bh / NH) * NH;
    const size_t base = (size_t)b * N_ * C_ + (size_t)tid * C_ + h * HD;
    __nv_bfloat162* dh = (__nv_bfloat162*)(g_AOhi + base);
    __nv_bfloat162* dl = (__nv_bfloat162*)(g_AOlo + base);
    const float* va = (const float*)acc;
#pragma unroll
    for (int j = 0; j < 16; j++) {
        float a0 = va[2 * j], a1 = va[2 * j + 1];
        __nv_bfloat16 h0 = __float2bfloat16_rn(a0);
        __nv_bfloat16 h1 = __float2bfloat16_rn(a1);
        __nv_bfloat162 hp; hp.x = h0; hp.y = h1;
        dh[j] = hp;
        __nv_bfloat162 lp;
        lp.x = __float2bfloat16_rn(a0 - __bfloat162float(h0));
        lp.y = __float2bfloat16_rn(a1 - __bfloat162float(h1));
        dl[j] = lp;
    }
}

// ---------------------------------------------------------------------------
extern "C" void kernel_launch(void* const* d_in, const int* in_sizes, int n_in,
                              void* d_out, int out_size)
{
    const float* x      = (const float*)d_in[0];
    const float* qkv_w  = (const float*)d_in[1];
    const float* qkv_b  = (const float*)d_in[2];
    const float* proj_w = (const float*)d_in[3];
    const float* proj_b = (const float*)d_in[4];
    float* out = (float*)d_out;

    cudaFuncSetAttribute(gemm_kernel<0>, cudaFuncAttributeMaxDynamicSharedMemorySize, SM_TOTAL);
    cudaFuncSetAttribute(gemm_kernel<1>, cudaFuncAttributeMaxDynamicSharedMemorySize, SM_TOTAL);
    cudaFuncSetAttribute(attn_kernel, cudaFuncAttributeMaxDynamicSharedMemorySize, 65536);

    convert_w<<<(H3 * C_ + C_ * C_ + 255) / 256, 256>>>(qkv_w, proj_w);
    convert_x<<<dim3(C_ / 32, N_ / 32, B_), 256>>>(x);
    gemm_kernel<0><<<dim3(H3 / 128, N_ / 128, B_), 256, SM_TOTAL>>>(qkv_b, nullptr);
    attn_kernel<<<B_ * NH, 256, 65536>>>();
    gemm_kernel<1><<<dim3(C_ / 128, N_ / 128, B_), 256, SM_TOTAL>>>(proj_b, out);
}

// round 6
// speedup vs baseline: 5.5094x; 2.1712x over previous
#include <cuda_runtime.h>
#include <cuda_bf16.h>
#include <cstdint>

#define B_  256
#define C_  384
#define N_  256
#define NH  12
#define HD  32
#define H3  1152

__device__ __constant__ float kSCALE = 0.17677669529663687f; // 32^-0.5

// ---------------- scratch (module-load allocated) ----------------
__device__ float g_Q[B_ * NH * N_ * HD];   // (b,h,n,d) fp32
__device__ float g_K[B_ * NH * N_ * HD];
__device__ float g_V[B_ * NH * N_ * HD];
__device__ __nv_bfloat16 g_Xhi[B_ * N_ * C_];   // (b,n,c)
__device__ __nv_bfloat16 g_Xlo[B_ * N_ * C_];
__device__ __nv_bfloat16 g_AOhi[B_ * N_ * C_];  // attention out (b,n,c)
__device__ __nv_bfloat16 g_AOlo[B_ * N_ * C_];
__device__ __nv_bfloat16 g_Wqhi[H3 * C_];
__device__ __nv_bfloat16 g_Wqlo[H3 * C_];
__device__ __nv_bfloat16 g_Wphi[C_ * C_];
__device__ __nv_bfloat16 g_Wplo[C_ * C_];

// ---------------- baseline-PTX helpers ----------
__device__ __forceinline__ uint32_t smem_u32(const void* p) {
    uint32_t a;
    asm("{ .reg .u64 t; cvta.to.shared.u64 t, %1; cvt.u32.u64 %0, t; }" : "=r"(a) : "l"(p));
    return a;
}
__device__ __forceinline__ void cp16(uint32_t dst, const void* src) {
    asm volatile("cp.async.cg.shared.global [%0], [%1], 16;" :: "r"(dst), "l"(src));
}
__device__ __forceinline__ void cp_commit() {
    asm volatile("cp.async.commit_group;" ::: "memory");
}
template <int N>
__device__ __forceinline__ void cp_wait() {
    asm volatile("cp.async.wait_group %0;" :: "n"(N) : "memory");
}
__device__ __forceinline__ void ldm_x4(uint32_t* r, uint32_t addr) {
    asm volatile("ldmatrix.sync.aligned.m8n8.x4.shared.b16 {%0,%1,%2,%3}, [%4];"
                 : "=r"(r[0]), "=r"(r[1]), "=r"(r[2]), "=r"(r[3]) : "r"(addr));
}
__device__ __forceinline__ void ldm_x4_t(uint32_t* r, uint32_t addr) {
    asm volatile("ldmatrix.sync.aligned.m8n8.x4.trans.shared.b16 {%0,%1,%2,%3}, [%4];"
                 : "=r"(r[0]), "=r"(r[1]), "=r"(r[2]), "=r"(r[3]) : "r"(addr));
}
__device__ __forceinline__ void mma16816(float* d, const uint32_t* a, uint32_t b0, uint32_t b1) {
    asm volatile("mma.sync.aligned.m16n8k16.row.col.f32.bf16.bf16.f32 "
                 "{%0,%1,%2,%3}, {%4,%5,%6,%7}, {%8,%9}, {%0,%1,%2,%3};"
                 : "+f"(d[0]), "+f"(d[1]), "+f"(d[2]), "+f"(d[3])
                 : "r"(a[0]), "r"(a[1]), "r"(a[2]), "r"(a[3]), "r"(b0), "r"(b1));
}

// Swizzled tile: 128 rows x 32 bf16 (64B/row), row-pairs in 128B lines,
// 16B chunks XOR-swizzled -> conflict-free ldmatrix.
__device__ __forceinline__ uint32_t tile_off(int row, int c) {
    return ((row >> 1) << 7) + ((((((row & 1) << 2) | c)) ^ ((row >> 1) & 7)) << 4);
}
// 256-row tile (two 8KB tiles)
__device__ __forceinline__ uint32_t off256(int row, int c) {
    return ((row >> 7) << 13) + tile_off(row & 127, c);
}
__device__ __forceinline__ void split2(float a, float b, uint32_t& hi, uint32_t& lo) {
    __nv_bfloat162 h = __floats2bfloat162_rn(a, b);
    hi = *(uint32_t*)&h;
    __nv_bfloat162 l = __floats2bfloat162_rn(a - __bfloat162float(h.x),
                                             b - __bfloat162float(h.y));
    lo = *(uint32_t*)&l;
}

#define OFF_AH 0
#define OFF_AL 8192
#define OFF_BH 16384
#define OFF_BL 24576
#define STAGE  32768
#define SM_TOTAL (2 * STAGE)

// ---------------------------------------------------------------------------
__global__ __launch_bounds__(256) void convert_w(const float* __restrict__ qw,
                                                 const float* __restrict__ pw)
{
    const int i = blockIdx.x * 256 + threadIdx.x;
    if (i < H3 * C_) {
        float v = qw[i];
        __nv_bfloat16 hi = __float2bfloat16_rn(v);
        g_Wqhi[i] = hi;
        g_Wqlo[i] = __float2bfloat16_rn(v - __bfloat162float(hi));
    }
    const int j = i - H3 * C_;
    if (j >= 0 && j < C_ * C_) {
        float v = pw[j];
        __nv_bfloat16 hi = __float2bfloat16_rn(v);
        g_Wphi[j] = hi;
        g_Wplo[j] = __float2bfloat16_rn(v - __bfloat162float(hi));
    }
}

__global__ __launch_bounds__(256) void convert_x(const float* __restrict__ x)
{
    __shared__ float tile[32][33];
    const int b = blockIdx.z, c0 = blockIdx.x * 32, n0 = blockIdx.y * 32;
    const int tx = threadIdx.x & 31, ty = threadIdx.x >> 5;
    const float* xb = x + (size_t)b * C_ * N_;
#pragma unroll
    for (int r = 0; r < 4; r++) {
        int c = ty + r * 8;
        tile[c][tx] = xb[(size_t)(c0 + c) * N_ + n0 + tx];
    }
    __syncthreads();
#pragma unroll
    for (int r = 0; r < 4; r++) {
        int n = ty + r * 8;
        float v = tile[tx][n];
        __nv_bfloat16 hi = __float2bfloat16_rn(v);
        size_t o = (size_t)b * N_ * C_ + (size_t)(n0 + n) * C_ + c0 + tx;
        g_Xhi[o] = hi;
        g_Xlo[o] = __float2bfloat16_rn(v - __bfloat162float(hi));
    }
}

// ---------------------------------------------------------------------------
// HMMA split-bf16 GEMM (as round 4, passing)
// ---------------------------------------------------------------------------
__device__ __forceinline__ void load_chunk(uint32_t sbase,
                                           const char* pAh, const char* pAl,
                                           const char* pBh, const char* pBl,
                                           int kB, int tid)
{
#pragma unroll
    for (int t = 0; t < 2; t++) {
        const int i = t * 256 + tid;
        const int row = i >> 2, c = i & 3;
        const uint32_t off = tile_off(row, c);
        const size_t g = (size_t)row * (C_ * 2) + kB + c * 16;
        cp16(sbase + OFF_AH + off, pAh + g);
        cp16(sbase + OFF_AL + off, pAl + g);
        cp16(sbase + OFF_BH + off, pBh + g);
        cp16(sbase + OFF_BL + off, pBl + g);
    }
    cp_commit();
}

__device__ __forceinline__ void compute_chunk(uint32_t sbase, int wm, int wn, int lane,
                                              float acc[2][8][4])
{
    const int ldrow = lane & 15;
    const int ldc   = lane >> 4;
#pragma unroll
    for (int kk = 0; kk < 2; kk++) {
        uint32_t ah[2][4], al[2][4], bh[4][4], bl[4][4];
        const int c = kk * 2 + ldc;
#pragma unroll
        for (int mi = 0; mi < 2; mi++) {
            const int row = wm * 32 + mi * 16 + ldrow;
            const uint32_t off = tile_off(row, c);
            ldm_x4(ah[mi], sbase + OFF_AH + off);
            ldm_x4(al[mi], sbase + OFF_AL + off);
        }
#pragma unroll
        for (int nj4 = 0; nj4 < 4; nj4++) {
            const int row = wn * 64 + nj4 * 16 + ldrow;
            const uint32_t off = tile_off(row, c);
            ldm_x4(bh[nj4], sbase + OFF_BH + off);
            ldm_x4(bl[nj4], sbase + OFF_BL + off);
        }
#pragma unroll
        for (int mi = 0; mi < 2; mi++)
#pragma unroll
            for (int nj = 0; nj < 8; nj++) {
                const int g = nj >> 1, p = nj & 1;
                mma16816(acc[mi][nj], ah[mi], bh[g][p], bh[g][p + 2]);
                mma16816(acc[mi][nj], ah[mi], bl[g][p], bl[g][p + 2]);
                mma16816(acc[mi][nj], al[mi], bh[g][p], bh[g][p + 2]);
            }
    }
}

template <int MODE>
__global__ __launch_bounds__(256) void gemm_kernel(const float* __restrict__ bias,
                                                   float* __restrict__ out)
{
    extern __shared__ char sm[];
    const uint32_t sb = smem_u32(sm);
    const int tid = threadIdx.x, lane = tid & 31, wid = tid >> 5;
    const int wm = wid >> 1, wn = wid & 1;
    const int b = blockIdx.z, m0 = blockIdx.y * 128, o0 = blockIdx.x * 128;

    const __nv_bfloat16* Ahi = (MODE == 0) ? g_Xhi : g_AOhi;
    const __nv_bfloat16* Alo = (MODE == 0) ? g_Xlo : g_AOlo;
    const __nv_bfloat16* Bhi = (MODE == 0) ? g_Wqhi : g_Wphi;
    const __nv_bfloat16* Blo = (MODE == 0) ? g_Wqlo : g_Wplo;

    const char* pAh = (const char*)(Ahi + ((size_t)b * N_ + m0) * C_);
    const char* pAl = (const char*)(Alo + ((size_t)b * N_ + m0) * C_);
    const char* pBh = (const char*)(Bhi + (size_t)o0 * C_);
    const char* pBl = (const char*)(Blo + (size_t)o0 * C_);

    float acc[2][8][4] = {};

    load_chunk(sb, pAh, pAl, pBh, pBl, 0, tid);

#pragma unroll 1
    for (int ck = 0; ck < 12; ck++) {
        if (ck < 11) {
            load_chunk(sb + ((ck + 1) & 1) * STAGE, pAh, pAl, pBh, pBl, (ck + 1) * 64, tid);
            cp_wait<1>();
        } else {
            cp_wait<0>();
        }
        __syncthreads();
        compute_chunk(sb + (ck & 1) * STAGE, wm, wn, lane, acc);
        __syncthreads();
    }

    if (MODE == 0) {
#pragma unroll
        for (int mi = 0; mi < 2; mi++) {
            const int m = m0 + wm * 32 + mi * 16 + (lane >> 2);
#pragma unroll
            for (int nj = 0; nj < 8; nj++) {
                const int o = o0 + wn * 64 + nj * 8 + (lane & 3) * 2;
                const int s = o / C_;
                const int rem = o - s * C_;
                const int h = rem >> 5, d = rem & 31;
                float* base = (s == 0) ? g_Q : (s == 1) ? g_K : g_V;
                const float b0 = bias[o], b1 = bias[o + 1];
                float* p0 = base + ((size_t)(b * NH + h) * N_ + m) * HD + d;
                *(float2*)p0 = make_float2(acc[mi][nj][0] + b0, acc[mi][nj][1] + b1);
                *(float2*)(p0 + 8 * HD) = make_float2(acc[mi][nj][2] + b0, acc[mi][nj][3] + b1);
            }
        }
    } else {
        float* ob = out + (size_t)b * C_ * N_;
#pragma unroll
        for (int mi = 0; mi < 2; mi++) {
            const int m = m0 + wm * 32 + mi * 16 + (lane >> 2);
#pragma unroll
            for (int nj = 0; nj < 8; nj++) {
                const int o = o0 + wn * 64 + nj * 8 + (lane & 3) * 2;
                const float b0 = bias[o], b1 = bias[o + 1];
                ob[(size_t)o * N_ + m]           = acc[mi][nj][0] + b0;
                ob[(size_t)(o + 1) * N_ + m]     = acc[mi][nj][1] + b1;
                ob[(size_t)o * N_ + m + 8]       = acc[mi][nj][2] + b0;
                ob[(size_t)(o + 1) * N_ + m + 8] = acc[mi][nj][3] + b1;
            }
        }
    }
}

// ---------------------------------------------------------------------------
// Tensor-core attention. One CTA per (b,h), 8 warps x 32 q-rows.
// Since q,k are L2-normalized and SCALE=0.1768: |s|<=0.1768 =>
//   - exp never over/underflows -> skip max subtraction (analytically equal)
//   - p in [2.7e-3, 5.6e-3]     -> clip(1e-6,1) provably inactive
// Single pass: S=QK^T (bf16 hi/lo 3-MMA), E=exp(S), rowsum(E), O+=E*V (3-MMA),
// O/=rowsum. E-fragment reuses S accumulator layout as MMA A operand.
// ---------------------------------------------------------------------------
#define SQH 0
#define SQL 16384
#define SKH 32768
#define SKL 49152
#define SVH 65536
#define SVL 81920
#define SM_ATT 98304

__device__ __forceinline__ void row_to_smem(uint32_t baseH, uint32_t baseL,
                                            int row, const float* v, float mul)
{
#pragma unroll
    for (int c = 0; c < 4; c++) {
        uint32_t wh[4], wl[4];
#pragma unroll
        for (int j = 0; j < 4; j++)
            split2(v[c * 8 + j * 2] * mul, v[c * 8 + j * 2 + 1] * mul, wh[j], wl[j]);
        const uint32_t off = off256(row, c);
        asm volatile("st.shared.v4.b32 [%0], {%1,%2,%3,%4};"
                     :: "r"(baseH + off), "r"(wh[0]), "r"(wh[1]), "r"(wh[2]), "r"(wh[3]));
        asm volatile("st.shared.v4.b32 [%0], {%1,%2,%3,%4};"
                     :: "r"(baseL + off), "r"(wl[0]), "r"(wl[1]), "r"(wl[2]), "r"(wl[3]));
    }
}

__global__ __launch_bounds__(256, 1) void attn_tc_kernel()
{
    extern __shared__ char sma[];
    const uint32_t sb = smem_u32(sma);
    const int bh = blockIdx.x, tid = threadIdx.x, lane = tid & 31, wid = tid >> 5;

    const float* Qg = g_Q + (size_t)bh * (N_ * HD);
    const float* Kg = g_K + (size_t)bh * (N_ * HD);
    const float* Vg = g_V + (size_t)bh * (N_ * HD);

    // ---- prep: normalize + split into swizzled smem (1 row / thread) ----
    {
        float r[32];
        float ss;
        // K
        ss = 0.f;
#pragma unroll
        for (int j = 0; j < 8; j++) {
            float4 t = ((const float4*)(Kg + tid * HD))[j];
            r[j * 4] = t.x; r[j * 4 + 1] = t.y; r[j * 4 + 2] = t.z; r[j * 4 + 3] = t.w;
            ss += t.x * t.x + t.y * t.y + t.z * t.z + t.w * t.w;
        }
        row_to_smem(sb + SKH, sb + SKL, tid, r, 1.f / fmaxf(sqrtf(ss), 1e-12f));
        // V
#pragma unroll
        for (int j = 0; j < 8; j++) {
            float4 t = ((const float4*)(Vg + tid * HD))[j];
            r[j * 4] = t.x; r[j * 4 + 1] = t.y; r[j * 4 + 2] = t.z; r[j * 4 + 3] = t.w;
        }
        row_to_smem(sb + SVH, sb + SVL, tid, r, 1.f);
        // Q (norm * SCALE)
        ss = 0.f;
#pragma unroll
        for (int j = 0; j < 8; j++) {
            float4 t = ((const float4*)(Qg + tid * HD))[j];
            r[j * 4] = t.x; r[j * 4 + 1] = t.y; r[j * 4 + 2] = t.z; r[j * 4 + 3] = t.w;
            ss += t.x * t.x + t.y * t.y + t.z * t.z + t.w * t.w;
        }
        row_to_smem(sb + SQH, sb + SQL, tid, r, kSCALE / fmaxf(sqrtf(ss), 1e-12f));
    }
    __syncthreads();

    // ---- Q fragments (held for whole kernel) ----
    const int m0 = wid * 32;
    const int ldrow = lane & 15, ldc = lane >> 4;
    uint32_t qh[2][2][4], ql[2][2][4];
#pragma unroll
    for (int mi = 0; mi < 2; mi++)
#pragma unroll
        for (int kk = 0; kk < 2; kk++) {
            const uint32_t off = off256(m0 + mi * 16 + ldrow, kk * 2 + ldc);
            ldm_x4(qh[mi][kk], sb + SQH + off);
            ldm_x4(ql[mi][kk], sb + SQL + off);
        }

    float O[2][4][4] = {};
    float rs[2][2] = {};

    // trans-ldmatrix lane addressing for V
    const int vrow = (lane & 7) + (((lane >> 4) & 1) << 3);
    const int vcsel = (lane >> 3) & 1;

#pragma unroll 1
    for (int ch = 0; ch < 8; ch++) {
        const int t0 = ch * 32;

        // K fragments for this chunk
        uint32_t kh[2][2][4], kl[2][2][4];
#pragma unroll
        for (int g = 0; g < 2; g++)
#pragma unroll
            for (int kk = 0; kk < 2; kk++) {
                const uint32_t off = off256(t0 + g * 16 + ldrow, kk * 2 + ldc);
                ldm_x4(kh[g][kk], sb + SKH + off);
                ldm_x4(kl[g][kk], sb + SKL + off);
            }

        // S = Q K^T  (3-product split)
        float S[2][4][4] = {};
#pragma unroll
        for (int kk = 0; kk < 2; kk++)
#pragma unroll
            for (int mi = 0; mi < 2; mi++)
#pragma unroll
                for (int nj = 0; nj < 4; nj++) {
                    const int g = nj >> 1, p = nj & 1;
                    mma16816(S[mi][nj], qh[mi][kk], kh[g][kk][p], kh[g][kk][p + 2]);
                    mma16816(S[mi][nj], qh[mi][kk], kl[g][kk][p], kl[g][kk][p + 2]);
                    mma16816(S[mi][nj], ql[mi][kk], kh[g][kk][p], kh[g][kk][p + 2]);
                }

        // E = exp(S); rowsum; repack C-frag -> A-frag (hi/lo)
        uint32_t eh[2][2][4], el[2][2][4];
#pragma unroll
        for (int mi = 0; mi < 2; mi++)
#pragma unroll
            for (int t = 0; t < 2; t++) {
                float e0 = __expf(S[mi][2 * t][0]);
                float e1 = __expf(S[mi][2 * t][1]);
                float e2 = __expf(S[mi][2 * t][2]);
                float e3 = __expf(S[mi][2 * t][3]);
                float f0 = __expf(S[mi][2 * t + 1][0]);
                float f1 = __expf(S[mi][2 * t + 1][1]);
                float f2 = __expf(S[mi][2 * t + 1][2]);
                float f3 = __expf(S[mi][2 * t + 1][3]);
                rs[mi][0] += e0 + e1 + f0 + f1;
                rs[mi][1] += e2 + e3 + f2 + f3;
                split2(e0, e1, eh[mi][t][0], el[mi][t][0]);
                split2(e2, e3, eh[mi][t][1], el[mi][t][1]);
                split2(f0, f1, eh[mi][t][2], el[mi][t][2]);
                split2(f2, f3, eh[mi][t][3], el[mi][t][3]);
            }

        // V fragments (trans) for this chunk
        uint32_t vh[2][2][4], vl[2][2][4];
#pragma unroll
        for (int t16 = 0; t16 < 2; t16++)
#pragma unroll
            for (int j = 0; j < 2; j++) {
                const uint32_t off = off256(t0 + t16 * 16 + vrow, j * 2 + vcsel);
                ldm_x4_t(vh[t16][j], sb + SVH + off);
                ldm_x4_t(vl[t16][j], sb + SVL + off);
            }

        // O += E V  (3-product split)
#pragma unroll
        for (int t16 = 0; t16 < 2; t16++)
#pragma unroll
            for (int mi = 0; mi < 2; mi++)
#pragma unroll
                for (int nd = 0; nd < 4; nd++) {
                    const int j = nd >> 1, p = nd & 1;
                    mma16816(O[mi][nd], eh[mi][t16], vh[t16][j][p], vh[t16][j][p + 2]);
                    mma16816(O[mi][nd], eh[mi][t16], vl[t16][j][p], vl[t16][j][p + 2]);
                    mma16816(O[mi][nd], el[mi][t16], vh[t16][j][p], vh[t16][j][p + 2]);
                }
    }

    // ---- rowsum reduce across quad, divide, store bf16 hi/lo ----
    const int b = bh / NH, h = bh - (bh / NH) * NH;
#pragma unroll
    for (int mi = 0; mi < 2; mi++) {
        float s0 = rs[mi][0], s1 = rs[mi][1];
        s0 += __shfl_xor_sync(0xffffffffu, s0, 1);
        s0 += __shfl_xor_sync(0xffffffffu, s0, 2);
        s1 += __shfl_xor_sync(0xffffffffu, s1, 1);
        s1 += __shfl_xor_sync(0xffffffffu, s1, 2);
        const float i0 = 1.f / s0, i1 = 1.f / s1;
        const int r1 = m0 + mi * 16 + (lane >> 2);
        const int r2 = r1 + 8;
#pragma unroll
        for (int nd = 0; nd < 4; nd++) {
            const int col = h * HD + nd * 8 + (lane & 3) * 2;
            uint32_t hi0, lo0, hi1, lo1;
            split2(O[mi][nd][0] * i0, O[mi][nd][1] * i0, hi0, lo0);
            split2(O[mi][nd][2] * i1, O[mi][nd][3] * i1, hi1, lo1);
            const size_t a1 = ((size_t)b * N_ + r1) * C_ + col;
            const size_t a2 = ((size_t)b * N_ + r2) * C_ + col;
            *(uint32_t*)(g_AOhi + a1) = hi0;
            *(uint32_t*)(g_AOlo + a1) = lo0;
            *(uint32_t*)(g_AOhi + a2) = hi1;
            *(uint32_t*)(g_AOlo + a2) = lo1;
        }
    }
}

// ---------------------------------------------------------------------------
extern "C" void kernel_launch(void* const* d_in, const int* in_sizes, int n_in,
                              void* d_out, int out_size)
{
    const float* x      = (const float*)d_in[0];
    const float* qkv_w  = (const float*)d_in[1];
    const float* qkv_b  = (const float*)d_in[2];
    const float* proj_w = (const float*)d_in[3];
    const float* proj_b = (const float*)d_in[4];
    float* out = (float*)d_out;

    cudaFuncSetAttribute(gemm_kernel<0>, cudaFuncAttributeMaxDynamicSharedMemorySize, SM_TOTAL);
    cudaFuncSetAttribute(gemm_kernel<1>, cudaFuncAttributeMaxDynamicSharedMemorySize, SM_TOTAL);
    cudaFuncSetAttribute(attn_tc_kernel, cudaFuncAttributeMaxDynamicSharedMemorySize, SM_ATT);

    convert_w<<<(H3 * C_ + C_ * C_ + 255) / 256, 256>>>(qkv_w, proj_w);
    convert_x<<<dim3(C_ / 32, N_ / 32, B_), 256>>>(x);
    gemm_kernel<0><<<dim3(H3 / 128, N_ / 128, B_), 256, SM_TOTAL>>>(qkv_b, nullptr);
    attn_tc_kernel<<<B_ * NH, 256, SM_ATT>>>();
    gemm_kernel<1><<<dim3(C_ / 128, N_ / 128, B_), 256, SM_TOTAL>>>(proj_b, out);
}

// round 7
// speedup vs baseline: 7.9337x; 1.4400x over previous
#include <cuda_runtime.h>
#include <cuda_fp16.h>
#include <cstdint>

#define B_  256
#define C_  384
#define N_  256
#define NH  12
#define HD  32
#define H3  1152

__device__ __constant__ float kSCALE = 0.17677669529663687f; // 32^-0.5

// ---------------- scratch (module-load allocated) ----------------
__device__ float g_Q[B_ * NH * N_ * HD];   // (b,h,n,d) fp32
__device__ float g_K[B_ * NH * N_ * HD];
__device__ float g_V[B_ * NH * N_ * HD];
__device__ __half g_Xhi[B_ * N_ * C_];     // (b,n,c) fp16 hi/lo split
__device__ __half g_Xlo[B_ * N_ * C_];
__device__ __half g_AOhi[B_ * N_ * C_];    // attention out (b,n,c)
__device__ __half g_AOlo[B_ * N_ * C_];
__device__ __half g_Wq[H3 * C_];           // weights: single fp16
__device__ __half g_Wp[C_ * C_];

// ---------------- baseline-PTX helpers ----------
__device__ __forceinline__ uint32_t smem_u32(const void* p) {
    uint32_t a;
    asm("{ .reg .u64 t; cvta.to.shared.u64 t, %1; cvt.u32.u64 %0, t; }" : "=r"(a) : "l"(p));
    return a;
}
__device__ __forceinline__ void cp16(uint32_t dst, const void* src) {
    asm volatile("cp.async.cg.shared.global [%0], [%1], 16;" :: "r"(dst), "l"(src));
}
__device__ __forceinline__ void cp_commit() {
    asm volatile("cp.async.commit_group;" ::: "memory");
}
template <int N>
__device__ __forceinline__ void cp_wait() {
    asm volatile("cp.async.wait_group %0;" :: "n"(N) : "memory");
}
__device__ __forceinline__ void ldm_x4(uint32_t* r, uint32_t addr) {
    asm volatile("ldmatrix.sync.aligned.m8n8.x4.shared.b16 {%0,%1,%2,%3}, [%4];"
                 : "=r"(r[0]), "=r"(r[1]), "=r"(r[2]), "=r"(r[3]) : "r"(addr));
}
__device__ __forceinline__ void ldm_x4_t(uint32_t* r, uint32_t addr) {
    asm volatile("ldmatrix.sync.aligned.m8n8.x4.trans.shared.b16 {%0,%1,%2,%3}, [%4];"
                 : "=r"(r[0]), "=r"(r[1]), "=r"(r[2]), "=r"(r[3]) : "r"(addr));
}
__device__ __forceinline__ void mma16816(float* d, const uint32_t* a, uint32_t b0, uint32_t b1) {
    asm volatile("mma.sync.aligned.m16n8k16.row.col.f32.f16.f16.f32 "
                 "{%0,%1,%2,%3}, {%4,%5,%6,%7}, {%8,%9}, {%0,%1,%2,%3};"
                 : "+f"(d[0]), "+f"(d[1]), "+f"(d[2]), "+f"(d[3])
                 : "r"(a[0]), "r"(a[1]), "r"(a[2]), "r"(a[3]), "r"(b0), "r"(b1));
}

// Swizzled tile: 128 rows x 32 halves (64B/row), row-pairs in 128B lines,
// 16B chunks XOR-swizzled -> conflict-free ldmatrix.
__device__ __forceinline__ uint32_t tile_off(int row, int c) {
    return ((row >> 1) << 7) + ((((((row & 1) << 2) | c)) ^ ((row >> 1) & 7)) << 4);
}
__device__ __forceinline__ uint32_t off256(int row, int c) {  // 256-row tile
    return ((row >> 7) << 13) + tile_off(row & 127, c);
}
__device__ __forceinline__ uint32_t pack2h(float a, float b) {
    __half2 h = __floats2half2_rn(a, b);
    return *(uint32_t*)&h;
}
__device__ __forceinline__ void split2h(float a, float b, uint32_t& hi, uint32_t& lo) {
    __half2 h = __floats2half2_rn(a, b);
    hi = *(uint32_t*)&h;
    __half2 l = __floats2half2_rn(a - __half2float(__low2half(h)),
                                  b - __half2float(__high2half(h)));
    lo = *(uint32_t*)&l;
}

#define OFF_AH 0
#define OFF_AL 8192
#define OFF_B  16384
#define STAGE  24576
#define SM_TOTAL (2 * STAGE)

// ---------------------------------------------------------------------------
__global__ __launch_bounds__(256) void convert_w(const float* __restrict__ qw,
                                                 const float* __restrict__ pw)
{
    const int i = blockIdx.x * 256 + threadIdx.x;
    if (i < H3 * C_) g_Wq[i] = __float2half_rn(qw[i]);
    const int j = i - H3 * C_;
    if (j >= 0 && j < C_ * C_) g_Wp[j] = __float2half_rn(pw[j]);
}

__global__ __launch_bounds__(256) void convert_x(const float* __restrict__ x)
{
    __shared__ float tile[32][33];
    const int b = blockIdx.z, c0 = blockIdx.x * 32, n0 = blockIdx.y * 32;
    const int tx = threadIdx.x & 31, ty = threadIdx.x >> 5;
    const float* xb = x + (size_t)b * C_ * N_;
#pragma unroll
    for (int r = 0; r < 4; r++) {
        int c = ty + r * 8;
        tile[c][tx] = xb[(size_t)(c0 + c) * N_ + n0 + tx];
    }
    __syncthreads();
#pragma unroll
    for (int r = 0; r < 4; r++) {
        int n = ty + r * 8;
        float v = tile[tx][n];
        __half hi = __float2half_rn(v);
        size_t o = (size_t)b * N_ * C_ + (size_t)(n0 + n) * C_ + c0 + tx;
        g_Xhi[o] = hi;
        g_Xlo[o] = __float2half_rn(v - __half2float(hi));
    }
}

// ---------------------------------------------------------------------------
// HMMA fp16 2-split GEMM:  D[m,o] = sum_c A[m,c]*B[o,c]  (A hi/lo, B single)
// CTA tile 128x128, K chunk 32, 8 warps of 32m x 64n, cp.async double buffer.
// MODE 0: A=g_X, B=g_Wq -> +bias, scatter g_Q/K/V (b,h,n,d)
// MODE 1: A=g_AO, B=g_Wp -> +bias, store out (b,o,n)
// ---------------------------------------------------------------------------
__device__ __forceinline__ void load_chunk(uint32_t sbase,
                                           const char* pAh, const char* pAl,
                                           const char* pB, int kB, int tid)
{
#pragma unroll
    for (int t = 0; t < 2; t++) {
        const int i = t * 256 + tid;
        const int row = i >> 2, c = i & 3;
        const uint32_t off = tile_off(row, c);
        const size_t g = (size_t)row * (C_ * 2) + kB + c * 16;
        cp16(sbase + OFF_AH + off, pAh + g);
        cp16(sbase + OFF_AL + off, pAl + g);
        cp16(sbase + OFF_B + off, pB + g);
    }
    cp_commit();
}

__device__ __forceinline__ void compute_chunk(uint32_t sbase, int wm, int wn, int lane,
                                              float acc[2][8][4])
{
    const int ldrow = lane & 15;
    const int ldc   = lane >> 4;
#pragma unroll
    for (int kk = 0; kk < 2; kk++) {
        uint32_t ah[2][4], al[2][4], bh[4][4];
        const int c = kk * 2 + ldc;
#pragma unroll
        for (int mi = 0; mi < 2; mi++) {
            const int row = wm * 32 + mi * 16 + ldrow;
            const uint32_t off = tile_off(row, c);
            ldm_x4(ah[mi], sbase + OFF_AH + off);
            ldm_x4(al[mi], sbase + OFF_AL + off);
        }
#pragma unroll
        for (int nj4 = 0; nj4 < 4; nj4++) {
            const int row = wn * 64 + nj4 * 16 + ldrow;
            const uint32_t off = tile_off(row, c);
            ldm_x4(bh[nj4], sbase + OFF_B + off);
        }
#pragma unroll
        for (int mi = 0; mi < 2; mi++)
#pragma unroll
            for (int nj = 0; nj < 8; nj++) {
                const int g = nj >> 1, p = nj & 1;
                mma16816(acc[mi][nj], ah[mi], bh[g][p], bh[g][p + 2]);
                mma16816(acc[mi][nj], al[mi], bh[g][p], bh[g][p + 2]);
            }
    }
}

template <int MODE>
__global__ __launch_bounds__(256) void gemm_kernel(const float* __restrict__ bias,
                                                   float* __restrict__ out)
{
    extern __shared__ char sm[];
    const uint32_t sb = smem_u32(sm);
    const int tid = threadIdx.x, lane = tid & 31, wid = tid >> 5;
    const int wm = wid >> 1, wn = wid & 1;
    const int b = blockIdx.z, m0 = blockIdx.y * 128, o0 = blockIdx.x * 128;

    const __half* Ahi = (MODE == 0) ? g_Xhi : g_AOhi;
    const __half* Alo = (MODE == 0) ? g_Xlo : g_AOlo;
    const __half* Bw  = (MODE == 0) ? g_Wq : g_Wp;

    const char* pAh = (const char*)(Ahi + ((size_t)b * N_ + m0) * C_);
    const char* pAl = (const char*)(Alo + ((size_t)b * N_ + m0) * C_);
    const char* pB  = (const char*)(Bw + (size_t)o0 * C_);

    float acc[2][8][4] = {};

    load_chunk(sb, pAh, pAl, pB, 0, tid);

#pragma unroll 1
    for (int ck = 0; ck < 12; ck++) {
        if (ck < 11) {
            load_chunk(sb + ((ck + 1) & 1) * STAGE, pAh, pAl, pB, (ck + 1) * 64, tid);
            cp_wait<1>();
        } else {
            cp_wait<0>();
        }
        __syncthreads();
        compute_chunk(sb + (ck & 1) * STAGE, wm, wn, lane, acc);
        __syncthreads();
    }

    if (MODE == 0) {
#pragma unroll
        for (int mi = 0; mi < 2; mi++) {
            const int m = m0 + wm * 32 + mi * 16 + (lane >> 2);
#pragma unroll
            for (int nj = 0; nj < 8; nj++) {
                const int o = o0 + wn * 64 + nj * 8 + (lane & 3) * 2;
                const int s = o / C_;
                const int rem = o - s * C_;
                const int h = rem >> 5, d = rem & 31;
                float* base = (s == 0) ? g_Q : (s == 1) ? g_K : g_V;
                const float b0 = bias[o], b1 = bias[o + 1];
                float* p0 = base + ((size_t)(b * NH + h) * N_ + m) * HD + d;
                *(float2*)p0 = make_float2(acc[mi][nj][0] + b0, acc[mi][nj][1] + b1);
                *(float2*)(p0 + 8 * HD) = make_float2(acc[mi][nj][2] + b0, acc[mi][nj][3] + b1);
            }
        }
    } else {
        float* ob = out + (size_t)b * C_ * N_;
#pragma unroll
        for (int mi = 0; mi < 2; mi++) {
            const int m = m0 + wm * 32 + mi * 16 + (lane >> 2);
#pragma unroll
            for (int nj = 0; nj < 8; nj++) {
                const int o = o0 + wn * 64 + nj * 8 + (lane & 3) * 2;
                const float b0 = bias[o], b1 = bias[o + 1];
                ob[(size_t)o * N_ + m]           = acc[mi][nj][0] + b0;
                ob[(size_t)(o + 1) * N_ + m]     = acc[mi][nj][1] + b1;
                ob[(size_t)o * N_ + m + 8]       = acc[mi][nj][2] + b0;
                ob[(size_t)(o + 1) * N_ + m + 8] = acc[mi][nj][3] + b1;
            }
        }
    }
}

// ---------------------------------------------------------------------------
// Tensor-core attention, fp16. One CTA per (b,h), 8 warps x 32 q-rows.
// |s|<=0.1768 (normalized q,k): skip max-subtraction; clip provably inactive.
// Q exact (hi/lo fp16), K,V single fp16; E exact (hi/lo fp16 repack).
// S = QK^T (2 MMA), E=exp(S), O += E V (2 MMA), O /= rowsum(E).
// ---------------------------------------------------------------------------
#define SQH 0
#define SQL 16384
#define SK  32768
#define SV  49152
#define SM_ATT 65536

__device__ __forceinline__ void row_to_smem_split(uint32_t baseH, uint32_t baseL,
                                                  int row, const float* v, float mul)
{
#pragma unroll
    for (int c = 0; c < 4; c++) {
        uint32_t wh[4], wl[4];
#pragma unroll
        for (int j = 0; j < 4; j++)
            split2h(v[c * 8 + j * 2] * mul, v[c * 8 + j * 2 + 1] * mul, wh[j], wl[j]);
        const uint32_t off = off256(row, c);
        asm volatile("st.shared.v4.b32 [%0], {%1,%2,%3,%4};"
                     :: "r"(baseH + off), "r"(wh[0]), "r"(wh[1]), "r"(wh[2]), "r"(wh[3]));
        asm volatile("st.shared.v4.b32 [%0], {%1,%2,%3,%4};"
                     :: "r"(baseL + off), "r"(wl[0]), "r"(wl[1]), "r"(wl[2]), "r"(wl[3]));
    }
}
__device__ __forceinline__ void row_to_smem_one(uint32_t base, int row,
                                                const float* v, float mul)
{
#pragma unroll
    for (int c = 0; c < 4; c++) {
        uint32_t w[4];
#pragma unroll
        for (int j = 0; j < 4; j++)
            w[j] = pack2h(v[c * 8 + j * 2] * mul, v[c * 8 + j * 2 + 1] * mul);
        const uint32_t off = off256(row, c);
        asm volatile("st.shared.v4.b32 [%0], {%1,%2,%3,%4};"
                     :: "r"(base + off), "r"(w[0]), "r"(w[1]), "r"(w[2]), "r"(w[3]));
    }
}

__global__ __launch_bounds__(256, 2) void attn_tc_kernel()
{
    extern __shared__ char sma[];
    const uint32_t sb = smem_u32(sma);
    const int bh = blockIdx.x, tid = threadIdx.x, lane = tid & 31, wid = tid >> 5;

    const float* Qg = g_Q + (size_t)bh * (N_ * HD);
    const float* Kg = g_K + (size_t)bh * (N_ * HD);
    const float* Vg = g_V + (size_t)bh * (N_ * HD);

    // ---- prep: normalize + convert into swizzled smem (1 row / thread) ----
    {
        float r[32];
        float ss;
        ss = 0.f;
#pragma unroll
        for (int j = 0; j < 8; j++) {
            float4 t = ((const float4*)(Kg + tid * HD))[j];
            r[j * 4] = t.x; r[j * 4 + 1] = t.y; r[j * 4 + 2] = t.z; r[j * 4 + 3] = t.w;
            ss += t.x * t.x + t.y * t.y + t.z * t.z + t.w * t.w;
        }
        row_to_smem_one(sb + SK, tid, r, 1.f / fmaxf(sqrtf(ss), 1e-12f));
#pragma unroll
        for (int j = 0; j < 8; j++) {
            float4 t = ((const float4*)(Vg + tid * HD))[j];
            r[j * 4] = t.x; r[j * 4 + 1] = t.y; r[j * 4 + 2] = t.z; r[j * 4 + 3] = t.w;
        }
        row_to_smem_one(sb + SV, tid, r, 1.f);
        ss = 0.f;
#pragma unroll
        for (int j = 0; j < 8; j++) {
            float4 t = ((const float4*)(Qg + tid * HD))[j];
            r[j * 4] = t.x; r[j * 4 + 1] = t.y; r[j * 4 + 2] = t.z; r[j * 4 + 3] = t.w;
            ss += t.x * t.x + t.y * t.y + t.z * t.z + t.w * t.w;
        }
        row_to_smem_split(sb + SQH, sb + SQL, tid, r, kSCALE / fmaxf(sqrtf(ss), 1e-12f));
    }
    __syncthreads();

    // ---- Q fragments (held for whole kernel) ----
    const int m0 = wid * 32;
    const int ldrow = lane & 15, ldc = lane >> 4;
    uint32_t qh[2][2][4], ql[2][2][4];
#pragma unroll
    for (int mi = 0; mi < 2; mi++)
#pragma unroll
        for (int kk = 0; kk < 2; kk++) {
            const uint32_t off = off256(m0 + mi * 16 + ldrow, kk * 2 + ldc);
            ldm_x4(qh[mi][kk], sb + SQH + off);
            ldm_x4(ql[mi][kk], sb + SQL + off);
        }

    float O[2][4][4] = {};
    float rs[2][2] = {};

    const int vrow = (lane & 7) + (((lane >> 4) & 1) << 3);
    const int vcsel = (lane >> 3) & 1;

#pragma unroll 1
    for (int ch = 0; ch < 8; ch++) {
        const int t0 = ch * 32;

        uint32_t kh[2][2][4];
#pragma unroll
        for (int g = 0; g < 2; g++)
#pragma unroll
            for (int kk = 0; kk < 2; kk++) {
                const uint32_t off = off256(t0 + g * 16 + ldrow, kk * 2 + ldc);
                ldm_x4(kh[g][kk], sb + SK + off);
            }

        float S[2][4][4] = {};
#pragma unroll
        for (int kk = 0; kk < 2; kk++)
#pragma unroll
            for (int mi = 0; mi < 2; mi++)
#pragma unroll
                for (int nj = 0; nj < 4; nj++) {
                    const int g = nj >> 1, p = nj & 1;
                    mma16816(S[mi][nj], qh[mi][kk], kh[g][kk][p], kh[g][kk][p + 2]);
                    mma16816(S[mi][nj], ql[mi][kk], kh[g][kk][p], kh[g][kk][p + 2]);
                }

        // E = exp(S); rowsum; repack C-frag -> A-frag (fp16 hi/lo)
        uint32_t eh[2][2][4], el[2][2][4];
#pragma unroll
        for (int mi = 0; mi < 2; mi++)
#pragma unroll
            for (int t = 0; t < 2; t++) {
                float e0 = __expf(S[mi][2 * t][0]);
                float e1 = __expf(S[mi][2 * t][1]);
                float e2 = __expf(S[mi][2 * t][2]);
                float e3 = __expf(S[mi][2 * t][3]);
                float f0 = __expf(S[mi][2 * t + 1][0]);
                float f1 = __expf(S[mi][2 * t + 1][1]);
                float f2 = __expf(S[mi][2 * t + 1][2]);
                float f3 = __expf(S[mi][2 * t + 1][3]);
                rs[mi][0] += e0 + e1 + f0 + f1;
                rs[mi][1] += e2 + e3 + f2 + f3;
                split2h(e0, e1, eh[mi][t][0], el[mi][t][0]);
                split2h(e2, e3, eh[mi][t][1], el[mi][t][1]);
                split2h(f0, f1, eh[mi][t][2], el[mi][t][2]);
                split2h(f2, f3, eh[mi][t][3], el[mi][t][3]);
            }

        uint32_t vh[2][2][4];
#pragma unroll
        for (int t16 = 0; t16 < 2; t16++)
#pragma unroll
            for (int j = 0; j < 2; j++) {
                const uint32_t off = off256(t0 + t16 * 16 + vrow, j * 2 + vcsel);
                ldm_x4_t(vh[t16][j], sb + SV + off);
            }

#pragma unroll
        for (int t16 = 0; t16 < 2; t16++)
#pragma unroll
            for (int mi = 0; mi < 2; mi++)
#pragma unroll
                for (int nd = 0; nd < 4; nd++) {
                    const int j = nd >> 1, p = nd & 1;
                    mma16816(O[mi][nd], eh[mi][t16], vh[t16][j][p], vh[t16][j][p + 2]);
                    mma16816(O[mi][nd], el[mi][t16], vh[t16][j][p], vh[t16][j][p + 2]);
                }
    }

    // ---- rowsum reduce across quad, divide, store fp16 hi/lo ----
    const int b = bh / NH, h = bh - (bh / NH) * NH;
#pragma unroll
    for (int mi = 0; mi < 2; mi++) {
        float s0 = rs[mi][0], s1 = rs[mi][1];
        s0 += __shfl_xor_sync(0xffffffffu, s0, 1);
        s0 += __shfl_xor_sync(0xffffffffu, s0, 2);
        s1 += __shfl_xor_sync(0xffffffffu, s1, 1);
        s1 += __shfl_xor_sync(0xffffffffu, s1, 2);
        const float i0 = 1.f / s0, i1 = 1.f / s1;
        const int r1 = m0 + mi * 16 + (lane >> 2);
        const int r2 = r1 + 8;
#pragma unroll
        for (int nd = 0; nd < 4; nd++) {
            const int col = h * HD + nd * 8 + (lane & 3) * 2;
            uint32_t hi0, lo0, hi1, lo1;
            split2h(O[mi][nd][0] * i0, O[mi][nd][1] * i0, hi0, lo0);
            split2h(O[mi][nd][2] * i1, O[mi][nd][3] * i1, hi1, lo1);
            const size_t a1 = ((size_t)b * N_ + r1) * C_ + col;
            const size_t a2 = ((size_t)b * N_ + r2) * C_ + col;
            *(uint32_t*)(g_AOhi + a1) = hi0;
            *(uint32_t*)(g_AOlo + a1) = lo0;
            *(uint32_t*)(g_AOhi + a2) = hi1;
            *(uint32_t*)(g_AOlo + a2) = lo1;
        }
    }
}

// ---------------------------------------------------------------------------
extern "C" void kernel_launch(void* const* d_in, const int* in_sizes, int n_in,
                              void* d_out, int out_size)
{
    const float* x      = (const float*)d_in[0];
    const float* qkv_w  = (const float*)d_in[1];
    const float* qkv_b  = (const float*)d_in[2];
    const float* proj_w = (const float*)d_in[3];
    const float* proj_b = (const float*)d_in[4];
    float* out = (float*)d_out;

    cudaFuncSetAttribute(gemm_kernel<0>, cudaFuncAttributeMaxDynamicSharedMemorySize, SM_TOTAL);
    cudaFuncSetAttribute(gemm_kernel<1>, cudaFuncAttributeMaxDynamicSharedMemorySize, SM_TOTAL);
    cudaFuncSetAttribute(attn_tc_kernel, cudaFuncAttributeMaxDynamicSharedMemorySize, SM_ATT);

    convert_w<<<(H3 * C_ + C_ * C_ + 255) / 256, 256>>>(qkv_w, proj_w);
    convert_x<<<dim3(C_ / 32, N_ / 32, B_), 256>>>(x);
    gemm_kernel<0><<<dim3(H3 / 128, N_ / 128, B_), 256, SM_TOTAL>>>(qkv_b, nullptr);
    attn_tc_kernel<<<B_ * NH, 256, SM_ATT>>>();
    gemm_kernel<1><<<dim3(C_ / 128, N_ / 128, B_), 256, SM_TOTAL>>>(proj_b, out);
}

// round 10
// speedup vs baseline: 13.2569x; 1.6710x over previous
#include <cuda_runtime.h>
#include <cuda_fp16.h>
#include <cstdint>

#define B_  256
#define C_  384
#define N_  256
#define NH  12
#define HD  32
#define H3  1152

__device__ __constant__ float kSCALE = 0.17677669529663687f; // 32^-0.5

// ---------------- scratch (module-load allocated) ----------------
__device__ __half g_Q[B_ * NH * N_ * HD];   // (b,h,n,d) fp16 (pre-norm)
__device__ __half g_K[B_ * NH * N_ * HD];
__device__ __half g_V[B_ * NH * N_ * HD];
__device__ __half g_X[B_ * N_ * C_];        // (b,n,c)
__device__ __half g_AO[B_ * N_ * C_];       // attention out (b,n,c)
__device__ __half g_Wq[H3 * C_];
__device__ __half g_Wp[C_ * C_];

// ---------------- baseline-PTX helpers ----------
__device__ __forceinline__ uint32_t smem_u32(const void* p) {
    uint32_t a;
    asm("{ .reg .u64 t; cvta.to.shared.u64 t, %1; cvt.u32.u64 %0, t; }" : "=r"(a) : "l"(p));
    return a;
}
__device__ __forceinline__ void cp16(uint32_t dst, const void* src) {
    asm volatile("cp.async.cg.shared.global [%0], [%1], 16;" :: "r"(dst), "l"(src));
}
__device__ __forceinline__ void cp_commit() {
    asm volatile("cp.async.commit_group;" ::: "memory");
}
template <int N>
__device__ __forceinline__ void cp_wait() {
    asm volatile("cp.async.wait_group %0;" :: "n"(N) : "memory");
}
__device__ __forceinline__ void ldm_x4(uint32_t* r, uint32_t addr) {
    asm volatile("ldmatrix.sync.aligned.m8n8.x4.shared.b16 {%0,%1,%2,%3}, [%4];"
                 : "=r"(r[0]), "=r"(r[1]), "=r"(r[2]), "=r"(r[3]) : "r"(addr));
}
__device__ __forceinline__ void ldm_x4_t(uint32_t* r, uint32_t addr) {
    asm volatile("ldmatrix.sync.aligned.m8n8.x4.trans.shared.b16 {%0,%1,%2,%3}, [%4];"
                 : "=r"(r[0]), "=r"(r[1]), "=r"(r[2]), "=r"(r[3]) : "r"(addr));
}
__device__ __forceinline__ void mma16816(float* d, const uint32_t* a, uint32_t b0, uint32_t b1) {
    asm volatile("mma.sync.aligned.m16n8k16.row.col.f32.f16.f16.f32 "
                 "{%0,%1,%2,%3}, {%4,%5,%6,%7}, {%8,%9}, {%0,%1,%2,%3};"
                 : "+f"(d[0]), "+f"(d[1]), "+f"(d[2]), "+f"(d[3])
                 : "r"(a[0]), "r"(a[1]), "r"(a[2]), "r"(a[3]), "r"(b0), "r"(b1));
}

// Swizzled tile: 128 rows x 32 halves (64B/row), row-pairs in 128B lines,
// 16B chunks XOR-swizzled -> conflict-free ldmatrix.
__device__ __forceinline__ uint32_t tile_off(int row, int c) {
    return ((row >> 1) << 7) + ((((((row & 1) << 2) | c)) ^ ((row >> 1) & 7)) << 4);
}
__device__ __forceinline__ uint32_t off256(int row, int c) {  // 256-row tile
    return ((row >> 7) << 13) + tile_off(row & 127, c);
}
__device__ __forceinline__ uint32_t pack2h(float a, float b) {
    __half2 h = __floats2half2_rn(a, b);
    return *(uint32_t*)&h;
}

#define OFF_A  0
#define OFF_B  8192
#define STAGE  16384
#define SM_TOTAL (2 * STAGE)

// ---------------------------------------------------------------------------
__global__ __launch_bounds__(256) void convert_w(const float* __restrict__ qw,
                                                 const float* __restrict__ pw)
{
    const int i = blockIdx.x * 256 + threadIdx.x;
    if (i < H3 * C_) g_Wq[i] = __float2half_rn(qw[i]);
    const int j = i - H3 * C_;
    if (j >= 0 && j < C_ * C_) g_Wp[j] = __float2half_rn(pw[j]);
}

__global__ __launch_bounds__(256) void convert_x(const float* __restrict__ x)
{
    __shared__ float tile[32][33];
    const int b = blockIdx.z, c0 = blockIdx.x * 32, n0 = blockIdx.y * 32;
    const int tx = threadIdx.x & 31, ty = threadIdx.x >> 5;
    const float* xb = x + (size_t)b * C_ * N_;
#pragma unroll
    for (int r = 0; r < 4; r++) {
        int c = ty + r * 8;
        tile[c][tx] = xb[(size_t)(c0 + c) * N_ + n0 + tx];
    }
    __syncthreads();
#pragma unroll
    for (int r = 0; r < 4; r++) {
        int n = ty + r * 8;
        size_t o = (size_t)b * N_ * C_ + (size_t)(n0 + n) * C_ + c0 + tx;
        g_X[o] = __float2half_rn(tile[tx][n]);
    }
}

// ---------------------------------------------------------------------------
// HMMA fp16 GEMM:  D[m,o] = sum_c A[m,c]*B[o,c]  (single fp16 operands)
// CTA tile 128x128, K chunk 32, 8 warps of 32m x 64n, cp.async double buffer.
// MODE 0: A=g_X, B=g_Wq -> +bias, scatter g_Q/K/V (b,h,n,d) fp16
// MODE 1: A=g_AO, B=g_Wp -> +bias, store out (b,o,n) fp32
// ---------------------------------------------------------------------------
__device__ __forceinline__ void load_chunk(uint32_t sbase,
                                           const char* pA, const char* pB,
                                           int kB, int tid)
{
#pragma unroll
    for (int t = 0; t < 2; t++) {
        const int i = t * 256 + tid;
        const int row = i >> 2, c = i & 3;
        const uint32_t off = tile_off(row, c);
        const size_t g = (size_t)row * (C_ * 2) + kB + c * 16;
        cp16(sbase + OFF_A + off, pA + g);
        cp16(sbase + OFF_B + off, pB + g);
    }
    cp_commit();
}

__device__ __forceinline__ void compute_chunk(uint32_t sbase, int wm, int wn, int lane,
                                              float acc[2][8][4])
{
    const int ldrow = lane & 15;
    const int ldc   = lane >> 4;
#pragma unroll
    for (int kk = 0; kk < 2; kk++) {
        uint32_t ah[2][4], bh[4][4];
        const int c = kk * 2 + ldc;
#pragma unroll
        for (int mi = 0; mi < 2; mi++) {
            const int row = wm * 32 + mi * 16 + ldrow;
            ldm_x4(ah[mi], sbase + OFF_A + tile_off(row, c));
        }
#pragma unroll
        for (int nj4 = 0; nj4 < 4; nj4++) {
            const int row = wn * 64 + nj4 * 16 + ldrow;
            ldm_x4(bh[nj4], sbase + OFF_B + tile_off(row, c));
        }
#pragma unroll
        for (int mi = 0; mi < 2; mi++)
#pragma unroll
            for (int nj = 0; nj < 8; nj++) {
                const int g = nj >> 1, p = nj & 1;
                mma16816(acc[mi][nj], ah[mi], bh[g][p], bh[g][p + 2]);
            }
    }
}

template <int MODE>
__global__ __launch_bounds__(256, 2) void gemm_kernel(const float* __restrict__ bias,
                                                      float* __restrict__ out)
{
    extern __shared__ char sm[];
    const uint32_t sb = smem_u32(sm);
    const int tid = threadIdx.x, lane = tid & 31, wid = tid >> 5;
    const int wm = wid >> 1, wn = wid & 1;
    const int b = blockIdx.z, m0 = blockIdx.y * 128, o0 = blockIdx.x * 128;

    const __half* A = (MODE == 0) ? g_X : g_AO;
    const __half* Bw = (MODE == 0) ? g_Wq : g_Wp;

    const char* pA = (const char*)(A + ((size_t)b * N_ + m0) * C_);
    const char* pB = (const char*)(Bw + (size_t)o0 * C_);

    float acc[2][8][4] = {};

    load_chunk(sb, pA, pB, 0, tid);

#pragma unroll 1
    for (int ck = 0; ck < 12; ck++) {
        if (ck < 11) {
            load_chunk(sb + ((ck + 1) & 1) * STAGE, pA, pB, (ck + 1) * 64, tid);
            cp_wait<1>();
        } else {
            cp_wait<0>();
        }
        __syncthreads();
        compute_chunk(sb + (ck & 1) * STAGE, wm, wn, lane, acc);
        __syncthreads();
    }

    if (MODE == 0) {
#pragma unroll
        for (int mi = 0; mi < 2; mi++) {
            const int m = m0 + wm * 32 + mi * 16 + (lane >> 2);
#pragma unroll
            for (int nj = 0; nj < 8; nj++) {
                const int o = o0 + wn * 64 + nj * 8 + (lane & 3) * 2;
                const int s = o / C_;
                const int rem = o - s * C_;
                const int h = rem >> 5, d = rem & 31;
                __half* base = (s == 0) ? g_Q : (s == 1) ? g_K : g_V;
                const float b0 = bias[o], b1 = bias[o + 1];
                __half* p0 = base + ((size_t)(b * NH + h) * N_ + m) * HD + d;
                *(uint32_t*)p0 = pack2h(acc[mi][nj][0] + b0, acc[mi][nj][1] + b1);
                *(uint32_t*)(p0 + 8 * HD) = pack2h(acc[mi][nj][2] + b0, acc[mi][nj][3] + b1);
            }
        }
    } else {
        float* ob = out + (size_t)b * C_ * N_;
#pragma unroll
        for (int mi = 0; mi < 2; mi++) {
            const int m = m0 + wm * 32 + mi * 16 + (lane >> 2);
#pragma unroll
            for (int nj = 0; nj < 8; nj++) {
                const int o = o0 + wn * 64 + nj * 8 + (lane & 3) * 2;
                const float b0 = bias[o], b1 = bias[o + 1];
                ob[(size_t)o * N_ + m]           = acc[mi][nj][0] + b0;
                ob[(size_t)(o + 1) * N_ + m]     = acc[mi][nj][1] + b1;
                ob[(size_t)o * N_ + m + 8]       = acc[mi][nj][2] + b0;
                ob[(size_t)(o + 1) * N_ + m + 8] = acc[mi][nj][3] + b1;
            }
        }
    }
}

// ---------------------------------------------------------------------------
// Tensor-core attention, single fp16. One CTA per (b,h), 8 warps x 32 q-rows.
// |s|<=0.1768 (normalized q,k): skip max-subtraction; clip provably inactive.
// S = QK^T (1 MMA), E=exp(S) fp16, O += E V (1 MMA), O /= rowsum(E).
// ---------------------------------------------------------------------------
#define SQ 0
#define SK 16384
#define SV 32768
#define SM_ATT 49152

__global__ __launch_bounds__(256, 2) void attn_tc_kernel()
{
    extern __shared__ char sma[];
    const uint32_t sb = smem_u32(sma);
    const int bh = blockIdx.x, tid = threadIdx.x, lane = tid & 31, wid = tid >> 5;

    const __half* Qg = g_Q + (size_t)bh * (N_ * HD);
    const __half* Kg = g_K + (size_t)bh * (N_ * HD);
    const __half* Vg = g_V + (size_t)bh * (N_ * HD);

    // ---- prep: 1 row / thread into swizzled smem ----
    {
        // V: raw copy (already fp16)
        uint4 raw[4];
#pragma unroll
        for (int c = 0; c < 4; c++) raw[c] = ((const uint4*)(Vg + tid * HD))[c];
#pragma unroll
        for (int c = 0; c < 4; c++) {
            const uint32_t off = off256(tid, c);
            asm volatile("st.shared.v4.b32 [%0], {%1,%2,%3,%4};"
                         :: "r"(sb + SV + off), "r"(raw[c].x), "r"(raw[c].y),
                            "r"(raw[c].z), "r"(raw[c].w));
        }
        // K: normalize
#pragma unroll
        for (int c = 0; c < 4; c++) raw[c] = ((const uint4*)(Kg + tid * HD))[c];
        {
            const __half2* h2 = (const __half2*)raw;
            float2 f[16];
            float ss = 0.f;
#pragma unroll
            for (int j = 0; j < 16; j++) {
                f[j] = __half22float2(h2[j]);
                ss += f[j].x * f[j].x + f[j].y * f[j].y;
            }
            const float inv = 1.f / fmaxf(sqrtf(ss), 1e-12f);
#pragma unroll
            for (int c = 0; c < 4; c++) {
                uint32_t w0 = pack2h(f[c * 4 + 0].x * inv, f[c * 4 + 0].y * inv);
                uint32_t w1 = pack2h(f[c * 4 + 1].x * inv, f[c * 4 + 1].y * inv);
                uint32_t w2 = pack2h(f[c * 4 + 2].x * inv, f[c * 4 + 2].y * inv);
                uint32_t w3 = pack2h(f[c * 4 + 3].x * inv, f[c * 4 + 3].y * inv);
                const uint32_t off = off256(tid, c);
                asm volatile("st.shared.v4.b32 [%0], {%1,%2,%3,%4};"
                             :: "r"(sb + SK + off), "r"(w0), "r"(w1), "r"(w2), "r"(w3));
            }
        }
        // Q: normalize * SCALE
#pragma unroll
        for (int c = 0; c < 4; c++) raw[c] = ((const uint4*)(Qg + tid * HD))[c];
        {
            const __half2* h2 = (const __half2*)raw;
            float2 f[16];
            float ss = 0.f;
#pragma unroll
            for (int j = 0; j < 16; j++) {
                f[j] = __half22float2(h2[j]);
                ss += f[j].x * f[j].x + f[j].y * f[j].y;
            }
            const float inv = kSCALE / fmaxf(sqrtf(ss), 1e-12f);
#pragma unroll
            for (int c = 0; c < 4; c++) {
                uint32_t w0 = pack2h(f[c * 4 + 0].x * inv, f[c * 4 + 0].y * inv);
                uint32_t w1 = pack2h(f[c * 4 + 1].x * inv, f[c * 4 + 1].y * inv);
                uint32_t w2 = pack2h(f[c * 4 + 2].x * inv, f[c * 4 + 2].y * inv);
                uint32_t w3 = pack2h(f[c * 4 + 3].x * inv, f[c * 4 + 3].y * inv);
                const uint32_t off = off256(tid, c);
                asm volatile("st.shared.v4.b32 [%0], {%1,%2,%3,%4};"
                             :: "r"(sb + SQ + off), "r"(w0), "r"(w1), "r"(w2), "r"(w3));
            }
        }
    }
    __syncthreads();

    // ---- Q fragments (held for whole kernel) ----
    const int m0 = wid * 32;
    const int ldrow = lane & 15, ldc = lane >> 4;
    uint32_t qh[2][2][4];
#pragma unroll
    for (int mi = 0; mi < 2; mi++)
#pragma unroll
        for (int kk = 0; kk < 2; kk++)
            ldm_x4(qh[mi][kk], sb + SQ + off256(m0 + mi * 16 + ldrow, kk * 2 + ldc));

    float O[2][4][4] = {};
    float rs[2][2] = {};

    // precomputed fragment base addresses (chunk 0); per-chunk delta is
    // (ch&3)*2048 + (ch>>2)*8192 because the swizzle is invariant under row+32
    uint32_t kbase[2][2], vbase[2][2];
    const int vrow = (lane & 7) + (((lane >> 4) & 1) << 3);
    const int vcsel = (lane >> 3) & 1;
#pragma unroll
    for (int g = 0; g < 2; g++)
#pragma unroll
        for (int kk = 0; kk < 2; kk++)
            kbase[g][kk] = sb + SK + off256(g * 16 + ldrow, kk * 2 + ldc);
#pragma unroll
    for (int t16 = 0; t16 < 2; t16++)
#pragma unroll
        for (int j = 0; j < 2; j++)
            vbase[t16][j] = sb + SV + off256(t16 * 16 + vrow, j * 2 + vcsel);

#pragma unroll 1
    for (int ch = 0; ch < 8; ch++) {
        const uint32_t choff = ((uint32_t)(ch & 3) << 11) + ((uint32_t)(ch >> 2) << 13);

        uint32_t kh[2][2][4];
#pragma unroll
        for (int g = 0; g < 2; g++)
#pragma unroll
            for (int kk = 0; kk < 2; kk++)
                ldm_x4(kh[g][kk], kbase[g][kk] + choff);

        float S[2][4][4] = {};
#pragma unroll
        for (int kk = 0; kk < 2; kk++)
#pragma unroll
            for (int mi = 0; mi < 2; mi++)
#pragma unroll
                for (int nj = 0; nj < 4; nj++) {
                    const int g = nj >> 1, p = nj & 1;
                    mma16816(S[mi][nj], qh[mi][kk], kh[g][kk][p], kh[g][kk][p + 2]);
                }

        // E = exp(S); rowsum; repack C-frag -> A-frag (single fp16)
        uint32_t eh[2][2][4];
#pragma unroll
        for (int mi = 0; mi < 2; mi++)
#pragma unroll
            for (int t = 0; t < 2; t++) {
                float e0 = __expf(S[mi][2 * t][0]);
                float e1 = __expf(S[mi][2 * t][1]);
                float e2 = __expf(S[mi][2 * t][2]);
                float e3 = __expf(S[mi][2 * t][3]);
                float f0 = __expf(S[mi][2 * t + 1][0]);
                float f1 = __expf(S[mi][2 * t + 1][1]);
                float f2 = __expf(S[mi][2 * t + 1][2]);
                float f3 = __expf(S[mi][2 * t + 1][3]);
                rs[mi][0] += e0 + e1 + f0 + f1;
                rs[mi][1] += e2 + e3 + f2 + f3;
                eh[mi][t][0] = pack2h(e0, e1);
                eh[mi][t][1] = pack2h(e2, e3);
                eh[mi][t][2] = pack2h(f0, f1);
                eh[mi][t][3] = pack2h(f2, f3);
            }

        uint32_t vh[2][2][4];
#pragma unroll
        for (int t16 = 0; t16 < 2; t16++)
#pragma unroll
            for (int j = 0; j < 2; j++)
                ldm_x4_t(vh[t16][j], vbase[t16][j] + choff);

#pragma unroll
        for (int t16 = 0; t16 < 2; t16++)
#pragma unroll
            for (int mi = 0; mi < 2; mi++)
#pragma unroll
                for (int nd = 0; nd < 4; nd++) {
                    const int j = nd >> 1, p = nd & 1;
                    mma16816(O[mi][nd], eh[mi][t16], vh[t16][j][p], vh[t16][j][p + 2]);
                }
    }

    // ---- rowsum reduce across quad, divide, store fp16 ----
    const int b = bh / NH, h = bh - (bh / NH) * NH;
#pragma unroll
    for (int mi = 0; mi < 2; mi++) {
        float s0 = rs[mi][0], s1 = rs[mi][1];
        s0 += __shfl_xor_sync(0xffffffffu, s0, 1);
        s0 += __shfl_xor_sync(0xffffffffu, s0, 2);
        s1 += __shfl_xor_sync(0xffffffffu, s1, 1);
        s1 += __shfl_xor_sync(0xffffffffu, s1, 2);
        const float i0 = 1.f / s0, i1 = 1.f / s1;
        const int r1 = m0 + mi * 16 + (lane >> 2);
        const int r2 = r1 + 8;
#pragma unroll
        for (int nd = 0; nd < 4; nd++) {
            const int col = h * HD + nd * 8 + (lane & 3) * 2;
            const size_t a1 = ((size_t)b * N_ + r1) * C_ + col;
            const size_t a2 = ((size_t)b * N_ + r2) * C_ + col;
            *(uint32_t*)(g_AO + a1) = pack2h(O[mi][nd][0] * i0, O[mi][nd][1] * i0);
            *(uint32_t*)(g_AO + a2) = pack2h(O[mi][nd][2] * i1, O[mi][nd][3] * i1);
        }
    }
}

// ---------------------------------------------------------------------------
extern "C" void kernel_launch(void* const* d_in, const int* in_sizes, int n_in,
                              void* d_out, int out_size)
{
    const float* x      = (const float*)d_in[0];
    const float* qkv_w  = (const float*)d_in[1];
    const float* qkv_b  = (const float*)d_in[2];
    const float* proj_w = (const float*)d_in[3];
    const float* proj_b = (const float*)d_in[4];
    float* out = (float*)d_out;

    cudaFuncSetAttribute(gemm_kernel<0>, cudaFuncAttributeMaxDynamicSharedMemorySize, SM_TOTAL);
    cudaFuncSetAttribute(gemm_kernel<1>, cudaFuncAttributeMaxDynamicSharedMemorySize, SM_TOTAL);
    cudaFuncSetAttribute(attn_tc_kernel, cudaFuncAttributeMaxDynamicSharedMemorySize, SM_ATT);

    convert_w<<<(H3 * C_ + C_ * C_ + 255) / 256, 256>>>(qkv_w, proj_w);
    convert_x<<<dim3(C_ / 32, N_ / 32, B_), 256>>>(x);
    gemm_kernel<0><<<dim3(H3 / 128, N_ / 128, B_), 256, SM_TOTAL>>>(qkv_b, nullptr);
    attn_tc_kernel<<<B_ * NH, 256, SM_ATT>>>();
    gemm_kernel<1><<<dim3(C_ / 128, N_ / 128, B_), 256, SM_TOTAL>>>(proj_b, out);
}

// round 11
// speedup vs baseline: 14.1889x; 1.0703x over previous
#include <cuda_runtime.h>
#include <cuda_fp16.h>
#include <cstdint>

#define B_  256
#define C_  384
#define N_  256
#define NH  12
#define HD  32
#define H3  1152

__device__ __constant__ float kSCALE = 0.17677669529663687f; // 32^-0.5

// ---------------- scratch (module-load allocated) ----------------
__device__ __half g_Q[B_ * NH * N_ * HD];   // (b,h,n,d) fp16 (pre-norm)
__device__ __half g_K[B_ * NH * N_ * HD];
__device__ __half g_V[B_ * NH * N_ * HD];
__device__ __half g_X[B_ * N_ * C_];        // (b,n,c)
__device__ __half g_AO[B_ * N_ * C_];       // attention out (b,n,c)
__device__ __half g_Wq[H3 * C_];
__device__ __half g_Wp[C_ * C_];

// ---------------- baseline-PTX helpers ----------
__device__ __forceinline__ uint32_t smem_u32(const void* p) {
    uint32_t a;
    asm("{ .reg .u64 t; cvta.to.shared.u64 t, %1; cvt.u32.u64 %0, t; }" : "=r"(a) : "l"(p));
    return a;
}
__device__ __forceinline__ void cp16(uint32_t dst, const void* src) {
    asm volatile("cp.async.cg.shared.global [%0], [%1], 16;" :: "r"(dst), "l"(src));
}
__device__ __forceinline__ void cp_commit() {
    asm volatile("cp.async.commit_group;" ::: "memory");
}
template <int N>
__device__ __forceinline__ void cp_wait() {
    asm volatile("cp.async.wait_group %0;" :: "n"(N) : "memory");
}
__device__ __forceinline__ void ldm_x4(uint32_t* r, uint32_t addr) {
    asm volatile("ldmatrix.sync.aligned.m8n8.x4.shared.b16 {%0,%1,%2,%3}, [%4];"
                 : "=r"(r[0]), "=r"(r[1]), "=r"(r[2]), "=r"(r[3]) : "r"(addr));
}
__device__ __forceinline__ void ldm_x4_t(uint32_t* r, uint32_t addr) {
    asm volatile("ldmatrix.sync.aligned.m8n8.x4.trans.shared.b16 {%0,%1,%2,%3}, [%4];"
                 : "=r"(r[0]), "=r"(r[1]), "=r"(r[2]), "=r"(r[3]) : "r"(addr));
}
__device__ __forceinline__ void mma16816(float* d, const uint32_t* a, uint32_t b0, uint32_t b1) {
    asm volatile("mma.sync.aligned.m16n8k16.row.col.f32.f16.f16.f32 "
                 "{%0,%1,%2,%3}, {%4,%5,%6,%7}, {%8,%9}, {%0,%1,%2,%3};"
                 : "+f"(d[0]), "+f"(d[1]), "+f"(d[2]), "+f"(d[3])
                 : "r"(a[0]), "r"(a[1]), "r"(a[2]), "r"(a[3]), "r"(b0), "r"(b1));
}

// Swizzled tile: 128 rows x 32 halves (64B/row), row-pairs in 128B lines,
// 16B chunks XOR-swizzled -> conflict-free ldmatrix.
__device__ __forceinline__ uint32_t tile_off(int row, int c) {
    return ((row >> 1) << 7) + ((((((row & 1) << 2) | c)) ^ ((row >> 1) & 7)) << 4);
}
__device__ __forceinline__ uint32_t off256(int row, int c) {  // 256-row tile
    return ((row >> 7) << 13) + tile_off(row & 127, c);
}
__device__ __forceinline__ uint32_t pack2h(float a, float b) {
    __half2 h = __floats2half2_rn(a, b);
    return *(uint32_t*)&h;
}

#define ONES2H 0x3C003C00u   // fp16 {1.0, 1.0} — constant all-ones B fragment

// GEMM stage layout: two K32 tiles per stage (A0,B0,A1,B1), 8KB each
#define OFF_A  0
#define OFF_B  8192
#define HSTEP  16384
#define STAGE  32768
#define SM_TOTAL (2 * STAGE)

// ---------------------------------------------------------------------------
__global__ __launch_bounds__(256) void convert_w(const float* __restrict__ qw,
                                                 const float* __restrict__ pw)
{
    const int i = blockIdx.x * 256 + threadIdx.x;
    if (i < H3 * C_) g_Wq[i] = __float2half_rn(qw[i]);
    const int j = i - H3 * C_;
    if (j >= 0 && j < C_ * C_) g_Wp[j] = __float2half_rn(pw[j]);
}

__global__ __launch_bounds__(256) void convert_x(const float* __restrict__ x)
{
    __shared__ float tile[32][33];
    const int b = blockIdx.z, c0 = blockIdx.x * 32, n0 = blockIdx.y * 32;
    const int tx = threadIdx.x & 31, ty = threadIdx.x >> 5;
    const float* xb = x + (size_t)b * C_ * N_;
#pragma unroll
    for (int r = 0; r < 4; r++) {
        int c = ty + r * 8;
        tile[c][tx] = xb[(size_t)(c0 + c) * N_ + n0 + tx];
    }
    __syncthreads();
#pragma unroll
    for (int r = 0; r < 4; r++) {
        int n = ty + r * 8;
        size_t o = (size_t)b * N_ * C_ + (size_t)(n0 + n) * C_ + c0 + tx;
        g_X[o] = __float2half_rn(tile[tx][n]);
    }
}

// ---------------------------------------------------------------------------
// HMMA fp16 GEMM:  D[m,o] = sum_c A[m,c]*B[o,c]  (single fp16 operands)
// CTA tile 128x128, stage = 2 x K32 chunks (half the barrier count),
// 8 warps of 32m x 64n, cp.async double buffer.
// MODE 0: A=g_X, B=g_Wq -> +bias, scatter g_Q/K/V (b,h,n,d) fp16
// MODE 1: A=g_AO, B=g_Wp -> +bias, store out (b,o,n) fp32
// ---------------------------------------------------------------------------
__device__ __forceinline__ void load_tile_pair(uint32_t sbase,
                                               const char* pA, const char* pB,
                                               int kB, int tid)
{
#pragma unroll
    for (int half = 0; half < 2; half++) {
        const uint32_t tb = sbase + half * HSTEP;
        const int kOfs = kB + half * 64;
#pragma unroll
        for (int t = 0; t < 2; t++) {
            const int i = t * 256 + tid;
            const int row = i >> 2, c = i & 3;
            const uint32_t off = tile_off(row, c);
            const size_t g = (size_t)row * (C_ * 2) + kOfs + c * 16;
            cp16(tb + OFF_A + off, pA + g);
            cp16(tb + OFF_B + off, pB + g);
        }
    }
    cp_commit();
}

__device__ __forceinline__ void compute_chunk(uint32_t sbase, int wm, int wn, int lane,
                                              float acc[2][8][4])
{
    const int ldrow = lane & 15;
    const int ldc   = lane >> 4;
#pragma unroll
    for (int kk = 0; kk < 2; kk++) {
        uint32_t ah[2][4], bh[4][4];
        const int c = kk * 2 + ldc;
#pragma unroll
        for (int mi = 0; mi < 2; mi++) {
            const int row = wm * 32 + mi * 16 + ldrow;
            ldm_x4(ah[mi], sbase + OFF_A + tile_off(row, c));
        }
#pragma unroll
        for (int nj4 = 0; nj4 < 4; nj4++) {
            const int row = wn * 64 + nj4 * 16 + ldrow;
            ldm_x4(bh[nj4], sbase + OFF_B + tile_off(row, c));
        }
#pragma unroll
        for (int mi = 0; mi < 2; mi++)
#pragma unroll
            for (int nj = 0; nj < 8; nj++) {
                const int g = nj >> 1, p = nj & 1;
                mma16816(acc[mi][nj], ah[mi], bh[g][p], bh[g][p + 2]);
            }
    }
}

template <int MODE>
__global__ __launch_bounds__(256, 2) void gemm_kernel(const float* __restrict__ bias,
                                                      float* __restrict__ out)
{
    extern __shared__ char sm[];
    const uint32_t sb = smem_u32(sm);
    const int tid = threadIdx.x, lane = tid & 31, wid = tid >> 5;
    const int wm = wid >> 1, wn = wid & 1;
    const int b = blockIdx.z, m0 = blockIdx.y * 128, o0 = blockIdx.x * 128;

    const __half* A = (MODE == 0) ? g_X : g_AO;
    const __half* Bw = (MODE == 0) ? g_Wq : g_Wp;

    const char* pA = (const char*)(A + ((size_t)b * N_ + m0) * C_);
    const char* pB = (const char*)(Bw + (size_t)o0 * C_);

    float acc[2][8][4] = {};

    load_tile_pair(sb, pA, pB, 0, tid);

#pragma unroll 1
    for (int st = 0; st < 6; st++) {
        if (st < 5) {
            load_tile_pair(sb + ((st + 1) & 1) * STAGE, pA, pB, (st + 1) * 128, tid);
            cp_wait<1>();
        } else {
            cp_wait<0>();
        }
        __syncthreads();
        const uint32_t base = sb + (st & 1) * STAGE;
        compute_chunk(base, wm, wn, lane, acc);
        compute_chunk(base + HSTEP, wm, wn, lane, acc);
        __syncthreads();
    }

    if (MODE == 0) {
#pragma unroll
        for (int mi = 0; mi < 2; mi++) {
            const int m = m0 + wm * 32 + mi * 16 + (lane >> 2);
#pragma unroll
            for (int nj = 0; nj < 8; nj++) {
                const int o = o0 + wn * 64 + nj * 8 + (lane & 3) * 2;
                const int s = o / C_;
                const int rem = o - s * C_;
                const int h = rem >> 5, d = rem & 31;
                __half* base = (s == 0) ? g_Q : (s == 1) ? g_K : g_V;
                const float b0 = bias[o], b1 = bias[o + 1];
                __half* p0 = base + ((size_t)(b * NH + h) * N_ + m) * HD + d;
                *(uint32_t*)p0 = pack2h(acc[mi][nj][0] + b0, acc[mi][nj][1] + b1);
                *(uint32_t*)(p0 + 8 * HD) = pack2h(acc[mi][nj][2] + b0, acc[mi][nj][3] + b1);
            }
        }
    } else {
        float* ob = out + (size_t)b * C_ * N_;
#pragma unroll
        for (int mi = 0; mi < 2; mi++) {
            const int m = m0 + wm * 32 + mi * 16 + (lane >> 2);
#pragma unroll
            for (int nj = 0; nj < 8; nj++) {
                const int o = o0 + wn * 64 + nj * 8 + (lane & 3) * 2;
                const float b0 = bias[o], b1 = bias[o + 1];
                ob[(size_t)o * N_ + m]           = acc[mi][nj][0] + b0;
                ob[(size_t)(o + 1) * N_ + m]     = acc[mi][nj][1] + b1;
                ob[(size_t)o * N_ + m + 8]       = acc[mi][nj][2] + b0;
                ob[(size_t)(o + 1) * N_ + m + 8] = acc[mi][nj][3] + b1;
            }
        }
    }
}

// ---------------------------------------------------------------------------
// Tensor-core attention, single fp16. One CTA per (b,h), 8 warps x 32 q-rows.
// |s|<=0.1768 (normalized q,k): skip max-subtraction; clip provably inactive.
// S = QK^T, E=exp(S) fp16, rowsum(E) via MMA with constant all-ones B
// fragment (saves 32 FADD/chunk + final shuffle reduce), O += E V, O /= rs.
// ---------------------------------------------------------------------------
#define SQ 0
#define SK 16384
#define SV 32768
#define SM_ATT 49152

__global__ __launch_bounds__(256, 2) void attn_tc_kernel()
{
    extern __shared__ char sma[];
    const uint32_t sb = smem_u32(sma);
    const int bh = blockIdx.x, tid = threadIdx.x, lane = tid & 31, wid = tid >> 5;

    const __half* Qg = g_Q + (size_t)bh * (N_ * HD);
    const __half* Kg = g_K + (size_t)bh * (N_ * HD);
    const __half* Vg = g_V + (size_t)bh * (N_ * HD);

    // ---- prep: 1 row / thread into swizzled smem ----
    {
        // V: raw copy (already fp16)
        uint4 raw[4];
#pragma unroll
        for (int c = 0; c < 4; c++) raw[c] = ((const uint4*)(Vg + tid * HD))[c];
#pragma unroll
        for (int c = 0; c < 4; c++) {
            const uint32_t off = off256(tid, c);
            asm volatile("st.shared.v4.b32 [%0], {%1,%2,%3,%4};"
                         :: "r"(sb + SV + off), "r"(raw[c].x), "r"(raw[c].y),
                            "r"(raw[c].z), "r"(raw[c].w));
        }
        // K: normalize
#pragma unroll
        for (int c = 0; c < 4; c++) raw[c] = ((const uint4*)(Kg + tid * HD))[c];
        {
            const __half2* h2 = (const __half2*)raw;
            float2 f[16];
            float ss = 0.f;
#pragma unroll
            for (int j = 0; j < 16; j++) {
                f[j] = __half22float2(h2[j]);
                ss += f[j].x * f[j].x + f[j].y * f[j].y;
            }
            const float inv = 1.f / fmaxf(sqrtf(ss), 1e-12f);
#pragma unroll
            for (int c = 0; c < 4; c++) {
                uint32_t w0 = pack2h(f[c * 4 + 0].x * inv, f[c * 4 + 0].y * inv);
                uint32_t w1 = pack2h(f[c * 4 + 1].x * inv, f[c * 4 + 1].y * inv);
                uint32_t w2 = pack2h(f[c * 4 + 2].x * inv, f[c * 4 + 2].y * inv);
                uint32_t w3 = pack2h(f[c * 4 + 3].x * inv, f[c * 4 + 3].y * inv);
                const uint32_t off = off256(tid, c);
                asm volatile("st.shared.v4.b32 [%0], {%1,%2,%3,%4};"
                             :: "r"(sb + SK + off), "r"(w0), "r"(w1), "r"(w2), "r"(w3));
            }
        }
        // Q: normalize * SCALE
#pragma unroll
        for (int c = 0; c < 4; c++) raw[c] = ((const uint4*)(Qg + tid * HD))[c];
        {
            const __half2* h2 = (const __half2*)raw;
            float2 f[16];
            float ss = 0.f;
#pragma unroll
            for (int j = 0; j < 16; j++) {
                f[j] = __half22float2(h2[j]);
                ss += f[j].x * f[j].x + f[j].y * f[j].y;
            }
            const float inv = kSCALE / fmaxf(sqrtf(ss), 1e-12f);
#pragma unroll
            for (int c = 0; c < 4; c++) {
                uint32_t w0 = pack2h(f[c * 4 + 0].x * inv, f[c * 4 + 0].y * inv);
                uint32_t w1 = pack2h(f[c * 4 + 1].x * inv, f[c * 4 + 1].y * inv);
                uint32_t w2 = pack2h(f[c * 4 + 2].x * inv, f[c * 4 + 2].y * inv);
                uint32_t w3 = pack2h(f[c * 4 + 3].x * inv, f[c * 4 + 3].y * inv);
                const uint32_t off = off256(tid, c);
                asm volatile("st.shared.v4.b32 [%0], {%1,%2,%3,%4};"
                             :: "r"(sb + SQ + off), "r"(w0), "r"(w1), "r"(w2), "r"(w3));
            }
        }
    }
    __syncthreads();

    // ---- Q fragments (held for whole kernel) ----
    const int m0 = wid * 32;
    const int ldrow = lane & 15, ldc = lane >> 4;
    uint32_t qh[2][2][4];
#pragma unroll
    for (int mi = 0; mi < 2; mi++)
#pragma unroll
        for (int kk = 0; kk < 2; kk++)
            ldm_x4(qh[mi][kk], sb + SQ + off256(m0 + mi * 16 + ldrow, kk * 2 + ldc));

    float O[2][4][4] = {};
    float rsO[2][4] = {};   // ones-MMA rowsum accumulator (c-frag per mi)

    // precomputed fragment base addresses (chunk 0); per-chunk delta is
    // (ch&3)*2048 + (ch>>2)*8192 because the swizzle is invariant under row+32
    uint32_t kbase[2][2], vbase[2][2];
    const int vrow = (lane & 7) + (((lane >> 4) & 1) << 3);
    const int vcsel = (lane >> 3) & 1;
#pragma unroll
    for (int g = 0; g < 2; g++)
#pragma unroll
        for (int kk = 0; kk < 2; kk++)
            kbase[g][kk] = sb + SK + off256(g * 16 + ldrow, kk * 2 + ldc);
#pragma unroll
    for (int t16 = 0; t16 < 2; t16++)
#pragma unroll
        for (int j = 0; j < 2; j++)
            vbase[t16][j] = sb + SV + off256(t16 * 16 + vrow, j * 2 + vcsel);

#pragma unroll 1
    for (int ch = 0; ch < 8; ch++) {
        const uint32_t choff = ((uint32_t)(ch & 3) << 11) + ((uint32_t)(ch >> 2) << 13);

        uint32_t kh[2][2][4];
#pragma unroll
        for (int g = 0; g < 2; g++)
#pragma unroll
            for (int kk = 0; kk < 2; kk++)
                ldm_x4(kh[g][kk], kbase[g][kk] + choff);

        float S[2][4][4] = {};
#pragma unroll
        for (int kk = 0; kk < 2; kk++)
#pragma unroll
            for (int mi = 0; mi < 2; mi++)
#pragma unroll
                for (int nj = 0; nj < 4; nj++) {
                    const int g = nj >> 1, p = nj & 1;
                    mma16816(S[mi][nj], qh[mi][kk], kh[g][kk][p], kh[g][kk][p + 2]);
                }

        // E = exp(S); repack C-frag -> A-frag (single fp16). rowsum via MMA.
        uint32_t eh[2][2][4];
#pragma unroll
        for (int mi = 0; mi < 2; mi++)
#pragma unroll
            for (int t = 0; t < 2; t++) {
                float e0 = __expf(S[mi][2 * t][0]);
                float e1 = __expf(S[mi][2 * t][1]);
                float e2 = __expf(S[mi][2 * t][2]);
                float e3 = __expf(S[mi][2 * t][3]);
                float f0 = __expf(S[mi][2 * t + 1][0]);
                float f1 = __expf(S[mi][2 * t + 1][1]);
                float f2 = __expf(S[mi][2 * t + 1][2]);
                float f3 = __expf(S[mi][2 * t + 1][3]);
                eh[mi][t][0] = pack2h(e0, e1);
                eh[mi][t][1] = pack2h(e2, e3);
                eh[mi][t][2] = pack2h(f0, f1);
                eh[mi][t][3] = pack2h(f2, f3);
            }

        uint32_t vh[2][2][4];
#pragma unroll
        for (int t16 = 0; t16 < 2; t16++)
#pragma unroll
            for (int j = 0; j < 2; j++)
                ldm_x4_t(vh[t16][j], vbase[t16][j] + choff);

#pragma unroll
        for (int t16 = 0; t16 < 2; t16++)
#pragma unroll
            for (int mi = 0; mi < 2; mi++) {
                // rowsum: E . ones  (constant B fragment, no load)
                mma16816(rsO[mi], eh[mi][t16], ONES2H, ONES2H);
#pragma unroll
                for (int nd = 0; nd < 4; nd++) {
                    const int j = nd >> 1, p = nd & 1;
                    mma16816(O[mi][nd], eh[mi][t16], vh[t16][j][p], vh[t16][j][p + 2]);
                }
            }
    }

    // ---- divide by rowsum (already per-lane via ones-MMA), store fp16 ----
    const int b = bh / NH, h = bh - (bh / NH) * NH;
#pragma unroll
    for (int mi = 0; mi < 2; mi++) {
        const float i0 = 1.f / rsO[mi][0];   // row r1 total
        const float i1 = 1.f / rsO[mi][2];   // row r2 total
        const int r1 = m0 + mi * 16 + (lane >> 2);
        const int r2 = r1 + 8;
#pragma unroll
        for (int nd = 0; nd < 4; nd++) {
            const int col = h * HD + nd * 8 + (lane & 3) * 2;
            const size_t a1 = ((size_t)b * N_ + r1) * C_ + col;
            const size_t a2 = ((size_t)b * N_ + r2) * C_ + col;
            *(uint32_t*)(g_AO + a1) = pack2h(O[mi][nd][0] * i0, O[mi][nd][1] * i0);
            *(uint32_t*)(g_AO + a2) = pack2h(O[mi][nd][2] * i1, O[mi][nd][3] * i1);
        }
    }
}

// ---------------------------------------------------------------------------
extern "C" void kernel_launch(void* const* d_in, const int* in_sizes, int n_in,
                              void* d_out, int out_size)
{
    const float* x      = (const float*)d_in[0];
    const float* qkv_w  = (const float*)d_in[1];
    const float* qkv_b  = (const float*)d_in[2];
    const float* proj_w = (const float*)d_in[3];
    const float* proj_b = (const float*)d_in[4];
    float* out = (float*)d_out;

    cudaFuncSetAttribute(gemm_kernel<0>, cudaFuncAttributeMaxDynamicSharedMemorySize, SM_TOTAL);
    cudaFuncSetAttribute(gemm_kernel<1>, cudaFuncAttributeMaxDynamicSharedMemorySize, SM_TOTAL);
    cudaFuncSetAttribute(attn_tc_kernel, cudaFuncAttributeMaxDynamicSharedMemorySize, SM_ATT);

    convert_w<<<(H3 * C_ + C_ * C_ + 255) / 256, 256>>>(qkv_w, proj_w);
    convert_x<<<dim3(C_ / 32, N_ / 32, B_), 256>>>(x);
    gemm_kernel<0><<<dim3(H3 / 128, N_ / 128, B_), 256, SM_TOTAL>>>(qkv_b, nullptr);
    attn_tc_kernel<<<B_ * NH, 256, SM_ATT>>>();
    gemm_kernel<1><<<dim3(C_ / 128, N_ / 128, B_), 256, SM_TOTAL>>>(proj_b, out);
}

// round 13
// speedup vs baseline: 14.7552x; 1.0399x over previous
#include <cuda_runtime.h>
#include <cuda_fp16.h>
#include <cstdint>

#define B_  256
#define C_  384
#define N_  256
#define NH  12
#define HD  32
#define H3  1152

// SCALE * log2(e): fold exp's base-2 conversion into Q normalization
__device__ __constant__ float kQS = 0.25507698105546733f;

// ---------------- scratch (module-load allocated) ----------------
__device__ __half g_Q[B_ * NH * N_ * HD];   // (b,h,n,d) fp16 (pre-norm)
__device__ __half g_K[B_ * NH * N_ * HD];
__device__ __half g_V[B_ * NH * N_ * HD];
__device__ __half g_X[B_ * N_ * C_];        // (b,n,c)
__device__ __half g_AO[B_ * N_ * C_];       // attention out (b,n,c)
__device__ __half g_Wq[H3 * C_];
__device__ __half g_Wp[C_ * C_];

// ---------------- baseline-PTX helpers ----------
__device__ __forceinline__ uint32_t smem_u32(const void* p) {
    uint32_t a;
    asm("{ .reg .u64 t; cvta.to.shared.u64 t, %1; cvt.u32.u64 %0, t; }" : "=r"(a) : "l"(p));
    return a;
}
__device__ __forceinline__ void cp16(uint32_t dst, const void* src) {
    asm volatile("cp.async.cg.shared.global [%0], [%1], 16;" :: "r"(dst), "l"(src));
}
__device__ __forceinline__ void cp_commit() {
    asm volatile("cp.async.commit_group;" ::: "memory");
}
template <int N>
__device__ __forceinline__ void cp_wait() {
    asm volatile("cp.async.wait_group %0;" :: "n"(N) : "memory");
}
__device__ __forceinline__ void ldm_x4(uint32_t* r, uint32_t addr) {
    asm volatile("ldmatrix.sync.aligned.m8n8.x4.shared.b16 {%0,%1,%2,%3}, [%4];"
                 : "=r"(r[0]), "=r"(r[1]), "=r"(r[2]), "=r"(r[3]) : "r"(addr));
}
__device__ __forceinline__ void ldm_x4_t(uint32_t* r, uint32_t addr) {
    asm volatile("ldmatrix.sync.aligned.m8n8.x4.trans.shared.b16 {%0,%1,%2,%3}, [%4];"
                 : "=r"(r[0]), "=r"(r[1]), "=r"(r[2]), "=r"(r[3]) : "r"(addr));
}
__device__ __forceinline__ void mma16816(float* d, const uint32_t* a, uint32_t b0, uint32_t b1) {
    asm volatile("mma.sync.aligned.m16n8k16.row.col.f32.f16.f16.f32 "
                 "{%0,%1,%2,%3}, {%4,%5,%6,%7}, {%8,%9}, {%0,%1,%2,%3};"
                 : "+f"(d[0]), "+f"(d[1]), "+f"(d[2]), "+f"(d[3])
                 : "r"(a[0]), "r"(a[1]), "r"(a[2]), "r"(a[3]), "r"(b0), "r"(b1));
}
__device__ __forceinline__ float ex2f(float x) {
    float y;
    asm("ex2.approx.ftz.f32 %0, %1;" : "=f"(y) : "f"(x));
    return y;
}

// Swizzled tile: 128 rows x 32 halves (64B/row), row-pairs in 128B lines,
// 16B chunks XOR-swizzled -> conflict-free ldmatrix.
__device__ __forceinline__ uint32_t tile_off(int row, int c) {
    return ((row >> 1) << 7) + ((((((row & 1) << 2) | c)) ^ ((row >> 1) & 7)) << 4);
}
__device__ __forceinline__ uint32_t off256(int row, int c) {  // 256-row tile
    return ((row >> 7) << 13) + tile_off(row & 127, c);
}
__device__ __forceinline__ uint32_t pack2h(float a, float b) {
    __half2 h = __floats2half2_rn(a, b);
    return *(uint32_t*)&h;
}

#define ONES2H 0x3C003C00u   // fp16 {1.0, 1.0} — constant all-ones B fragment

// GEMM stage layout: two K32 tiles per stage (A0,B0,A1,B1), 8KB each
#define OFF_A  0
#define OFF_B  8192
#define HSTEP  16384
#define STAGE  32768
#define SM_TOTAL (2 * STAGE)

// ---------------------------------------------------------------------------
// Fused converts: blocks [0, 24576) transpose+convert x; rest convert weights.
// ---------------------------------------------------------------------------
#define XBLOCKS (B_ * 96)   // 12 c-tiles x 8 n-tiles per b

__global__ __launch_bounds__(256) void convert_all(const float* __restrict__ x,
                                                   const float* __restrict__ qw,
                                                   const float* __restrict__ pw)
{
    if (blockIdx.x < XBLOCKS) {
        __shared__ float tile[32][33];
        const int bid = blockIdx.x;
        const int b = bid / 96, r = bid - b * 96;
        const int c0 = (r % 12) * 32, n0 = (r / 12) * 32;
        const int tx = threadIdx.x & 31, ty = threadIdx.x >> 5;
        const float* xb = x + (size_t)b * C_ * N_;
#pragma unroll
        for (int rr = 0; rr < 4; rr++) {
            int c = ty + rr * 8;
            tile[c][tx] = xb[(size_t)(c0 + c) * N_ + n0 + tx];
        }
        __syncthreads();
#pragma unroll
        for (int rr = 0; rr < 4; rr++) {
            int n = ty + rr * 8;
            size_t o = (size_t)b * N_ * C_ + (size_t)(n0 + n) * C_ + c0 + tx;
            g_X[o] = __float2half_rn(tile[tx][n]);
        }
    } else {
        const int i = (blockIdx.x - XBLOCKS) * 256 + threadIdx.x;
        if (i < H3 * C_) g_Wq[i] = __float2half_rn(qw[i]);
        const int j = i - H3 * C_;
        if (j >= 0 && j < C_ * C_) g_Wp[j] = __float2half_rn(pw[j]);
    }
}

// ---------------------------------------------------------------------------
// HMMA fp16 GEMM:  D[m,o] = sum_c A[m,c]*B[o,c]  (single fp16 operands)
// CTA tile 128x128, stage = 2 x K32 chunks, 8 warps of 32m x 64n,
// cp.async double buffer. Fragment smem offsets hoisted out of the loop.
// MODE 0: A=g_X, B=g_Wq -> +bias, scatter g_Q/K/V (b,h,n,d) fp16
// MODE 1: A=g_AO, B=g_Wp -> +bias, store out (b,o,n) fp32
// ---------------------------------------------------------------------------
__device__ __forceinline__ void load_tile_pair(uint32_t sbase,
                                               const char* pA, const char* pB,
                                               int kB, int tid)
{
#pragma unroll
    for (int half = 0; half < 2; half++) {
        const uint32_t tb = sbase + half * HSTEP;
        const int kOfs = kB + half * 64;
#pragma unroll
        for (int t = 0; t < 2; t++) {
            const int i = t * 256 + tid;
            const int row = i >> 2, c = i & 3;
            const uint32_t off = tile_off(row, c);
            const size_t g = (size_t)row * (C_ * 2) + kOfs + c * 16;
            cp16(tb + OFF_A + off, pA + g);
            cp16(tb + OFF_B + off, pB + g);
        }
    }
    cp_commit();
}

__device__ __forceinline__ void compute_chunk(uint32_t base,
                                              const uint32_t aoff[2][2],
                                              const uint32_t boff[2][4],
                                              float acc[2][8][4])
{
#pragma unroll
    for (int kk = 0; kk < 2; kk++) {
        uint32_t ah[2][4], bh[4][4];
#pragma unroll
        for (int mi = 0; mi < 2; mi++)
            ldm_x4(ah[mi], base + aoff[kk][mi]);
#pragma unroll
        for (int nj4 = 0; nj4 < 4; nj4++)
            ldm_x4(bh[nj4], base + boff[kk][nj4]);
#pragma unroll
        for (int mi = 0; mi < 2; mi++)
#pragma unroll
            for (int nj = 0; nj < 8; nj++) {
                const int g = nj >> 1, p = nj & 1;
                mma16816(acc[mi][nj], ah[mi], bh[g][p], bh[g][p + 2]);
            }
    }
}

template <int MODE>
__global__ __launch_bounds__(256, 2) void gemm_kernel(const float* __restrict__ bias,
                                                      float* __restrict__ out)
{
    extern __shared__ char sm[];
    const uint32_t sb = smem_u32(sm);
    const int tid = threadIdx.x, lane = tid & 31, wid = tid >> 5;
    const int wm = wid >> 1, wn = wid & 1;
    const int b = blockIdx.z, m0 = blockIdx.y * 128, o0 = blockIdx.x * 128;

    const __half* A = (MODE == 0) ? g_X : g_AO;
    const __half* Bw = (MODE == 0) ? g_Wq : g_Wp;

    const char* pA = (const char*)(A + ((size_t)b * N_ + m0) * C_);
    const char* pB = (const char*)(Bw + (size_t)o0 * C_);

    // hoisted fragment offsets (invariant across stages/halves)
    const int ldrow = lane & 15, ldc = lane >> 4;
    uint32_t aoff[2][2], boff[2][4];
#pragma unroll
    for (int kk = 0; kk < 2; kk++) {
        const int c = kk * 2 + ldc;
#pragma unroll
        for (int mi = 0; mi < 2; mi++)
            aoff[kk][mi] = OFF_A + tile_off(wm * 32 + mi * 16 + ldrow, c);
#pragma unroll
        for (int nj4 = 0; nj4 < 4; nj4++)
            boff[kk][nj4] = OFF_B + tile_off(wn * 64 + nj4 * 16 + ldrow, c);
    }

    float acc[2][8][4] = {};

    load_tile_pair(sb, pA, pB, 0, tid);

#pragma unroll 1
    for (int st = 0; st < 6; st++) {
        if (st < 5) {
            load_tile_pair(sb + ((st + 1) & 1) * STAGE, pA, pB, (st + 1) * 128, tid);
            cp_wait<1>();
        } else {
            cp_wait<0>();
        }
        __syncthreads();
        const uint32_t base = sb + (st & 1) * STAGE;
        compute_chunk(base, aoff, boff, acc);
        compute_chunk(base + HSTEP, aoff, boff, acc);
        __syncthreads();
    }

    if (MODE == 0) {
#pragma unroll
        for (int mi = 0; mi < 2; mi++) {
            const int m = m0 + wm * 32 + mi * 16 + (lane >> 2);
#pragma unroll
            for (int nj = 0; nj < 8; nj++) {
                const int o = o0 + wn * 64 + nj * 8 + (lane & 3) * 2;
                const int s = o / C_;
                const int rem = o - s * C_;
                const int h = rem >> 5, d = rem & 31;
                __half* base = (s == 0) ? g_Q : (s == 1) ? g_K : g_V;
                const float b0 = bias[o], b1 = bias[o + 1];
                __half* p0 = base + ((size_t)(b * NH + h) * N_ + m) * HD + d;
                *(uint32_t*)p0 = pack2h(acc[mi][nj][0] + b0, acc[mi][nj][1] + b1);
                *(uint32_t*)(p0 + 8 * HD) = pack2h(acc[mi][nj][2] + b0, acc[mi][nj][3] + b1);
            }
        }
    } else {
        float* ob = out + (size_t)b * C_ * N_;
#pragma unroll
        for (int mi = 0; mi < 2; mi++) {
            const int m = m0 + wm * 32 + mi * 16 + (lane >> 2);
#pragma unroll
            for (int nj = 0; nj < 8; nj++) {
                const int o = o0 + wn * 64 + nj * 8 + (lane & 3) * 2;
                const float b0 = bias[o], b1 = bias[o + 1];
                ob[(size_t)o * N_ + m]           = acc[mi][nj][0] + b0;
                ob[(size_t)(o + 1) * N_ + m]     = acc[mi][nj][1] + b1;
                ob[(size_t)o * N_ + m + 8]       = acc[mi][nj][2] + b0;
                ob[(size_t)(o + 1) * N_ + m + 8] = acc[mi][nj][3] + b1;
            }
        }
    }
}

// ---------------------------------------------------------------------------
// Tensor-core attention, single fp16. One CTA per (b,h), 8 warps x 32 q-rows.
// Q pre-scaled by SCALE*log2(e): E = 2^S via bare ex2 (no FMUL).
// |s| small (normalized q,k): no max-subtraction; clip provably inactive.
// rowsum(E) via ones-MMA. O += E V. O /= rowsum.
// ---------------------------------------------------------------------------
#define SQ 0
#define SK 16384
#define SV 32768
#define SM_ATT 49152

__global__ __launch_bounds__(256, 2) void attn_tc_kernel()
{
    extern __shared__ char sma[];
    const uint32_t sb = smem_u32(sma);
    const int bh = blockIdx.x, tid = threadIdx.x, lane = tid & 31, wid = tid >> 5;

    const __half* Qg = g_Q + (size_t)bh * (N_ * HD);
    const __half* Kg = g_K + (size_t)bh * (N_ * HD);
    const __half* Vg = g_V + (size_t)bh * (N_ * HD);

    // ---- prep: 1 row / thread into swizzled smem ----
    {
        // V: raw copy (already fp16)
        uint4 raw[4];
#pragma unroll
        for (int c = 0; c < 4; c++) raw[c] = ((const uint4*)(Vg + tid * HD))[c];
#pragma unroll
        for (int c = 0; c < 4; c++) {
            const uint32_t off = off256(tid, c);
            asm volatile("st.shared.v4.b32 [%0], {%1,%2,%3,%4};"
                         :: "r"(sb + SV + off), "r"(raw[c].x), "r"(raw[c].y),
                            "r"(raw[c].z), "r"(raw[c].w));
        }
        // K: normalize
#pragma unroll
        for (int c = 0; c < 4; c++) raw[c] = ((const uint4*)(Kg + tid * HD))[c];
        {
            const __half2* h2 = (const __half2*)raw;
            float2 f[16];
            float ss = 0.f;
#pragma unroll
            for (int j = 0; j < 16; j++) {
                f[j] = __half22float2(h2[j]);
                ss += f[j].x * f[j].x + f[j].y * f[j].y;
            }
            const float inv = 1.f / fmaxf(sqrtf(ss), 1e-12f);
#pragma unroll
            for (int c = 0; c < 4; c++) {
                uint32_t w0 = pack2h(f[c * 4 + 0].x * inv, f[c * 4 + 0].y * inv);
                uint32_t w1 = pack2h(f[c * 4 + 1].x * inv, f[c * 4 + 1].y * inv);
                uint32_t w2 = pack2h(f[c * 4 + 2].x * inv, f[c * 4 + 2].y * inv);
                uint32_t w3 = pack2h(f[c * 4 + 3].x * inv, f[c * 4 + 3].y * inv);
                const uint32_t off = off256(tid, c);
                asm volatile("st.shared.v4.b32 [%0], {%1,%2,%3,%4};"
                             :: "r"(sb + SK + off), "r"(w0), "r"(w1), "r"(w2), "r"(w3));
            }
        }
        // Q: normalize * SCALE * log2(e)
#pragma unroll
        for (int c = 0; c < 4; c++) raw[c] = ((const uint4*)(Qg + tid * HD))[c];
        {
            const __half2* h2 = (const __half2*)raw;
            float2 f[16];
            float ss = 0.f;
#pragma unroll
            for (int j = 0; j < 16; j++) {
                f[j] = __half22float2(h2[j]);
                ss += f[j].x * f[j].x + f[j].y * f[j].y;
            }
            const float inv = kQS / fmaxf(sqrtf(ss), 1e-12f);
#pragma unroll
            for (int c = 0; c < 4; c++) {
                uint32_t w0 = pack2h(f[c * 4 + 0].x * inv, f[c * 4 + 0].y * inv);
                uint32_t w1 = pack2h(f[c * 4 + 1].x * inv, f[c * 4 + 1].y * inv);
                uint32_t w2 = pack2h(f[c * 4 + 2].x * inv, f[c * 4 + 2].y * inv);
                uint32_t w3 = pack2h(f[c * 4 + 3].x * inv, f[c * 4 + 3].y * inv);
                const uint32_t off = off256(tid, c);
                asm volatile("st.shared.v4.b32 [%0], {%1,%2,%3,%4};"
                             :: "r"(sb + SQ + off), "r"(w0), "r"(w1), "r"(w2), "r"(w3));
            }
        }
    }
    __syncthreads();

    // ---- Q fragments (held for whole kernel) ----
    const int m0 = wid * 32;
    const int ldrow = lane & 15, ldc = lane >> 4;
    uint32_t qh[2][2][4];
#pragma unroll
    for (int mi = 0; mi < 2; mi++)
#pragma unroll
        for (int kk = 0; kk < 2; kk++)
            ldm_x4(qh[mi][kk], sb + SQ + off256(m0 + mi * 16 + ldrow, kk * 2 + ldc));

    float O[2][4][4] = {};
    float rsO[2][4] = {};   // ones-MMA rowsum accumulator

    // precomputed fragment base addresses; per-chunk delta is
    // (ch&3)*2048 + (ch>>2)*8192 (swizzle invariant under row+32)
    uint32_t kbase[2][2], vbase[2][2];
    const int vrow = (lane & 7) + (((lane >> 4) & 1) << 3);
    const int vcsel = (lane >> 3) & 1;
#pragma unroll
    for (int g = 0; g < 2; g++)
#pragma unroll
        for (int kk = 0; kk < 2; kk++)
            kbase[g][kk] = sb + SK + off256(g * 16 + ldrow, kk * 2 + ldc);
#pragma unroll
    for (int t16 = 0; t16 < 2; t16++)
#pragma unroll
        for (int j = 0; j < 2; j++)
            vbase[t16][j] = sb + SV + off256(t16 * 16 + vrow, j * 2 + vcsel);

#pragma unroll 1
    for (int ch = 0; ch < 8; ch++) {
        const uint32_t choff = ((uint32_t)(ch & 3) << 11) + ((uint32_t)(ch >> 2) << 13);

        uint32_t kh[2][2][4];
#pragma unroll
        for (int g = 0; g < 2; g++)
#pragma unroll
            for (int kk = 0; kk < 2; kk++)
                ldm_x4(kh[g][kk], kbase[g][kk] + choff);

        float S[2][4][4] = {};
#pragma unroll
        for (int kk = 0; kk < 2; kk++)
#pragma unroll
            for (int mi = 0; mi < 2; mi++)
#pragma unroll
                for (int nj = 0; nj < 4; nj++) {
                    const int g = nj >> 1, p = nj & 1;
                    mma16816(S[mi][nj], qh[mi][kk], kh[g][kk][p], kh[g][kk][p + 2]);
                }

        // E = 2^S (bare ex2); repack C-frag -> A-frag (single fp16)
        uint32_t eh[2][2][4];
#pragma unroll
        for (int mi = 0; mi < 2; mi++)
#pragma unroll
            for (int t = 0; t < 2; t++) {
                float e0 = ex2f(S[mi][2 * t][0]);
                float e1 = ex2f(S[mi][2 * t][1]);
                float e2 = ex2f(S[mi][2 * t][2]);
                float e3 = ex2f(S[mi][2 * t][3]);
                float f0 = ex2f(S[mi][2 * t + 1][0]);
                float f1 = ex2f(S[mi][2 * t + 1][1]);
                float f2 = ex2f(S[mi][2 * t + 1][2]);
                float f3 = ex2f(S[mi][2 * t + 1][3]);
                eh[mi][t][0] = pack2h(e0, e1);
                eh[mi][t][1] = pack2h(e2, e3);
                eh[mi][t][2] = pack2h(f0, f1);
                eh[mi][t][3] = pack2h(f2, f3);
            }

        uint32_t vh[2][2][4];
#pragma unroll
        for (int t16 = 0; t16 < 2; t16++)
#pragma unroll
            for (int j = 0; j < 2; j++)
                ldm_x4_t(vh[t16][j], vbase[t16][j] + choff);

#pragma unroll
        for (int t16 = 0; t16 < 2; t16++)
#pragma unroll
            for (int mi = 0; mi < 2; mi++) {
                mma16816(rsO[mi], eh[mi][t16], ONES2H, ONES2H);
#pragma unroll
                for (int nd = 0; nd < 4; nd++) {
                    const int j = nd >> 1, p = nd & 1;
                    mma16816(O[mi][nd], eh[mi][t16], vh[t16][j][p], vh[t16][j][p + 2]);
                }
            }
    }

    // ---- divide by rowsum, store fp16 ----
    const int b = bh / NH, h = bh - (bh / NH) * NH;
#pragma unroll
    for (int mi = 0; mi < 2; mi++) {
        const float i0 = 1.f / rsO[mi][0];
        const float i1 = 1.f / rsO[mi][2];
        const int r1 = m0 + mi * 16 + (lane >> 2);
        const int r2 = r1 + 8;
#pragma unroll
        for (int nd = 0; nd < 4; nd++) {
            const int col = h * HD + nd * 8 + (lane & 3) * 2;
            const size_t a1 = ((size_t)b * N_ + r1) * C_ + col;
            const size_t a2 = ((size_t)b * N_ + r2) * C_ + col;
            *(uint32_t*)(g_AO + a1) = pack2h(O[mi][nd][0] * i0, O[mi][nd][1] * i0);
            *(uint32_t*)(g_AO + a2) = pack2h(O[mi][nd][2] * i1, O[mi][nd][3] * i1);
        }
    }
}

// ---------------------------------------------------------------------------
extern "C" void kernel_launch(void* const* d_in, const int* in_sizes, int n_in,
                              void* d_out, int out_size)
{
    const float* x      = (const float*)d_in[0];
    const float* qkv_w  = (const float*)d_in[1];
    const float* qkv_b  = (const float*)d_in[2];
    const float* proj_w = (const float*)d_in[3];
    const float* proj_b = (const float*)d_in[4];
    float* out = (float*)d_out;

    cudaFuncSetAttribute(gemm_kernel<0>, cudaFuncAttributeMaxDynamicSharedMemorySize, SM_TOTAL);
    cudaFuncSetAttribute(gemm_kernel<1>, cudaFuncAttributeMaxDynamicSharedMemorySize, SM_TOTAL);
    cudaFuncSetAttribute(attn_tc_kernel, cudaFuncAttributeMaxDynamicSharedMemorySize, SM_ATT);

    const int wblocks = (H3 * C_ + C_ * C_ + 255) / 256;
    convert_all<<<XBLOCKS + wblocks, 256>>>(x, qkv_w, proj_w);
    gemm_kernel<0><<<dim3(H3 / 128, N_ / 128, B_), 256, SM_TOTAL>>>(qkv_b, nullptr);
    attn_tc_kernel<<<B_ * NH, 256, SM_ATT>>>();
    gemm_kernel<1><<<dim3(C_ / 128, N_ / 128, B_), 256, SM_TOTAL>>>(proj_b, out);
}